// round 1
// baseline (speedup 1.0000x reference)
#include <cuda_runtime.h>

#define HIDDEN 1024
#define FOURH  4096
#define HEADS  16
#define HD     64
#define SEQ    2048
#define BATCH  2
#define MTOT   (BATCH * SEQ)   // 4096
#define MAXSEQ 2048

// Scratch (allocation-free rule: __device__ globals)
__device__ float g_act[(size_t)MTOT * FOURH];    // silu(x@W1+b1): [4096, 4096]
__device__ float g_gated[(size_t)MTOT * HIDDEN]; // attn_out * U : [4096, 1024]

__device__ __forceinline__ float silu_f(float x) {
    return x / (1.0f + __expf(-x));
}

// ---------------------------------------------------------------------------
// Generic fp32 GEMM: C[M,N] = A[M,K] @ B[K,N] + bias[N], optional SiLU.
// 64x64 block tile, BK=16, 256 threads, 4x4 per thread.
// ---------------------------------------------------------------------------
__global__ __launch_bounds__(256) void gemm_kernel(
    const float* __restrict__ A, const float* __restrict__ B,
    const float* __restrict__ bias, float* __restrict__ C,
    int N, int K, int do_silu)
{
    __shared__ float As[16][68];  // As[kk][m], stride 68 keeps float4 alignment
    __shared__ float Bs[16][64];  // Bs[kk][n]

    const int tid = threadIdx.x;
    const int tx  = tid & 15;
    const int ty  = tid >> 4;
    const int m0  = blockIdx.y << 6;
    const int n0  = blockIdx.x << 6;

    const int la_row = tid >> 2;          // 0..63
    const int la_k   = (tid & 3) << 2;    // 0,4,8,12
    const int lb_k   = tid >> 4;          // 0..15
    const int lb_n   = (tid & 15) << 2;   // 0..60

    const float* Ap = A + (size_t)(m0 + la_row) * K + la_k;
    const float* Bp = B + (size_t)lb_k * N + n0 + lb_n;

    float acc[4][4] = {};

    for (int k0 = 0; k0 < K; k0 += 16) {
        float4 av = *(const float4*)(Ap + k0);
        float4 bv = *(const float4*)(Bp + (size_t)k0 * N);
        As[la_k + 0][la_row] = av.x;
        As[la_k + 1][la_row] = av.y;
        As[la_k + 2][la_row] = av.z;
        As[la_k + 3][la_row] = av.w;
        *(float4*)&Bs[lb_k][lb_n] = bv;
        __syncthreads();

        #pragma unroll
        for (int kk = 0; kk < 16; kk++) {
            float4 a4 = *(const float4*)&As[kk][ty << 2];
            float4 b4 = *(const float4*)&Bs[kk][tx << 2];
            acc[0][0] += a4.x * b4.x; acc[0][1] += a4.x * b4.y;
            acc[0][2] += a4.x * b4.z; acc[0][3] += a4.x * b4.w;
            acc[1][0] += a4.y * b4.x; acc[1][1] += a4.y * b4.y;
            acc[1][2] += a4.y * b4.z; acc[1][3] += a4.y * b4.w;
            acc[2][0] += a4.z * b4.x; acc[2][1] += a4.z * b4.y;
            acc[2][2] += a4.z * b4.z; acc[2][3] += a4.z * b4.w;
            acc[3][0] += a4.w * b4.x; acc[3][1] += a4.w * b4.y;
            acc[3][2] += a4.w * b4.z; acc[3][3] += a4.w * b4.w;
        }
        __syncthreads();
    }

    const int cn = n0 + (tx << 2);
    float4 bb = *(const float4*)&bias[cn];
    #pragma unroll
    for (int i = 0; i < 4; i++) {
        int row = m0 + (ty << 2) + i;
        float4 r;
        r.x = acc[i][0] + bb.x;
        r.y = acc[i][1] + bb.y;
        r.z = acc[i][2] + bb.z;
        r.w = acc[i][3] + bb.w;
        if (do_silu) {
            r.x = silu_f(r.x); r.y = silu_f(r.y);
            r.z = silu_f(r.z); r.w = silu_f(r.w);
        }
        *(float4*)&C[(size_t)row * N + cn] = r;
    }
}

// ---------------------------------------------------------------------------
// Fused HSTU attention: per (b, head, q-tile of 64), causal flash-style loop.
//   S = silu(Q Kᵀ * scale + rel_bias), masked; out += S @ V; gated = out * U.
// smem: Qt[d][qi] (transposed), KS buffer (Kt[d][kj], reused as Ss[qi][kj]),
//       Vs[kj][dd]. All 64x68 fp32 -> 52224 B dynamic smem.
// ---------------------------------------------------------------------------
__global__ __launch_bounds__(256) void attn_kernel(const float* __restrict__ rel_table)
{
    const int qt = gridDim.x - 1 - blockIdx.x;  // long tiles launch first
    const int h  = blockIdx.y;
    const int b  = blockIdx.z;

    extern __shared__ float sm[];
    float* Qt = sm;              // [64][68]  Qt[d*68 + qi]
    float* KS = sm + 64 * 68;    // [64][68]  Kt[d*68 + kj]  then Ss[qi*68 + kj]
    float* Vs = sm + 2 * 64 * 68;// [64][68]  Vs[kj*68 + dd]

    const int tid  = threadIdx.x;
    const int tx4  = (tid & 15) << 2;
    const int ty4  = (tid >> 4) << 2;
    const int lrow = tid >> 2;           // 0..63
    const int lc   = (tid & 3) << 4;     // 0,16,32,48
    const float scale = 0.125f;          // 1/sqrt(64)

    // Load Q tile (transposed into Qt)
    {
        const float* src = g_act + (size_t)(b * SEQ + qt * 64 + lrow) * FOURH
                           + HIDDEN + h * HD + lc;
        #pragma unroll
        for (int u = 0; u < 4; u++) {
            float4 v = *(const float4*)(src + 4 * u);
            int c = lc + 4 * u;
            Qt[(c + 0) * 68 + lrow] = v.x;
            Qt[(c + 1) * 68 + lrow] = v.y;
            Qt[(c + 2) * 68 + lrow] = v.z;
            Qt[(c + 3) * 68 + lrow] = v.w;
        }
    }

    float acc[4][4] = {};

    for (int kt = 0; kt <= qt; kt++) {
        __syncthreads();  // prev iter done reading KS/Vs (also orders Q-load, iter 0)
        {
            const float* ksrc = g_act + (size_t)(b * SEQ + kt * 64 + lrow) * FOURH
                                + 2 * HIDDEN + h * HD + lc;
            const float* vsrc = ksrc + HIDDEN;  // V chunk is +1024 cols after K
            #pragma unroll
            for (int u = 0; u < 4; u++) {
                float4 kv = *(const float4*)(ksrc + 4 * u);
                int c = lc + 4 * u;
                KS[(c + 0) * 68 + lrow] = kv.x;
                KS[(c + 1) * 68 + lrow] = kv.y;
                KS[(c + 2) * 68 + lrow] = kv.z;
                KS[(c + 3) * 68 + lrow] = kv.w;
                *(float4*)&Vs[lrow * 68 + c] = *(const float4*)(vsrc + 4 * u);
            }
        }
        __syncthreads();

        // s[4][4] = Q Kᵀ  (both operands read as conflict-free LDS.128)
        float s[4][4] = {};
        #pragma unroll 8
        for (int d = 0; d < 64; d++) {
            float4 q4 = *(const float4*)&Qt[d * 68 + ty4];
            float4 k4 = *(const float4*)&KS[d * 68 + tx4];
            s[0][0] += q4.x * k4.x; s[0][1] += q4.x * k4.y;
            s[0][2] += q4.x * k4.z; s[0][3] += q4.x * k4.w;
            s[1][0] += q4.y * k4.x; s[1][1] += q4.y * k4.y;
            s[1][2] += q4.y * k4.z; s[1][3] += q4.y * k4.w;
            s[2][0] += q4.z * k4.x; s[2][1] += q4.z * k4.y;
            s[2][2] += q4.z * k4.z; s[2][3] += q4.z * k4.w;
            s[3][0] += q4.w * k4.x; s[3][1] += q4.w * k4.y;
            s[3][2] += q4.w * k4.z; s[3][3] += q4.w * k4.w;
        }

        // bias gather + silu + causal mask
        #pragma unroll
        for (int i = 0; i < 4; i++) {
            int qg = qt * 64 + ty4 + i;
            #pragma unroll
            for (int j = 0; j < 4; j++) {
                int kg = kt * 64 + tx4 + j;
                float v = s[i][j] * scale
                        + __ldg(&rel_table[(size_t)(qg - kg + MAXSEQ - 1) * HEADS + h]);
                v = silu_f(v);
                s[i][j] = (kg <= qg) ? v : 0.0f;
            }
        }

        __syncthreads();  // everyone done reading Kt
        #pragma unroll
        for (int i = 0; i < 4; i++) {
            float4 r = make_float4(s[i][0], s[i][1], s[i][2], s[i][3]);
            *(float4*)&KS[(ty4 + i) * 68 + tx4] = r;  // KS now holds Ss
        }
        __syncthreads();

        // out += Ss @ Vs
        #pragma unroll 8
        for (int kj = 0; kj < 64; kj++) {
            float4 v4 = *(const float4*)&Vs[kj * 68 + tx4];
            float s0 = KS[(ty4 + 0) * 68 + kj];
            float s1 = KS[(ty4 + 1) * 68 + kj];
            float s2 = KS[(ty4 + 2) * 68 + kj];
            float s3 = KS[(ty4 + 3) * 68 + kj];
            acc[0][0] += s0 * v4.x; acc[0][1] += s0 * v4.y;
            acc[0][2] += s0 * v4.z; acc[0][3] += s0 * v4.w;
            acc[1][0] += s1 * v4.x; acc[1][1] += s1 * v4.y;
            acc[1][2] += s1 * v4.z; acc[1][3] += s1 * v4.w;
            acc[2][0] += s2 * v4.x; acc[2][1] += s2 * v4.y;
            acc[2][2] += s2 * v4.z; acc[2][3] += s2 * v4.w;
            acc[3][0] += s3 * v4.x; acc[3][1] += s3 * v4.y;
            acc[3][2] += s3 * v4.z; acc[3][3] += s3 * v4.w;
        }
    }

    // Epilogue: gated = out * U, written to g_gated
    #pragma unroll
    for (int i = 0; i < 4; i++) {
        size_t row = (size_t)(b * SEQ + qt * 64 + ty4 + i);
        float4 u4 = *(const float4*)&g_act[row * FOURH + h * HD + tx4];
        float4 r  = make_float4(acc[i][0] * u4.x, acc[i][1] * u4.y,
                                acc[i][2] * u4.z, acc[i][3] * u4.w);
        *(float4*)&g_gated[row * HIDDEN + h * HD + tx4] = r;
    }
}

// ---------------------------------------------------------------------------
// Launch: GEMM1+silu -> fused attention+gate -> GEMM2+bias
// Inputs (metadata order): x, W1, b1, W2, b2, rel_table, attn_mask(ignored:
// it is always the causal tril by construction; causality applied analytically)
// ---------------------------------------------------------------------------
extern "C" void kernel_launch(void* const* d_in, const int* in_sizes, int n_in,
                              void* d_out, int out_size)
{
    const float* x   = (const float*)d_in[0];
    const float* W1  = (const float*)d_in[1];
    const float* b1  = (const float*)d_in[2];
    const float* W2  = (const float*)d_in[3];
    const float* b2  = (const float*)d_in[4];
    const float* rel = (const float*)d_in[5];
    float* out = (float*)d_out;

    float* act_p = nullptr;
    float* gated_p = nullptr;
    cudaGetSymbolAddress((void**)&act_p, g_act);
    cudaGetSymbolAddress((void**)&gated_p, g_gated);

    const int smem_attn = 3 * 64 * 68 * (int)sizeof(float);  // 52224 B
    cudaFuncSetAttribute(attn_kernel, cudaFuncAttributeMaxDynamicSharedMemorySize,
                         smem_attn);

    // GEMM1: activated = silu(x @ W1 + b1), [4096, 4096]
    gemm_kernel<<<dim3(FOURH / 64, MTOT / 64), 256>>>(x, W1, b1, act_p,
                                                      FOURH, HIDDEN, 1);
    // Fused attention + gating -> g_gated [4096, 1024]
    attn_kernel<<<dim3(SEQ / 64, HEADS, BATCH), 256, smem_attn>>>(rel);
    // GEMM2: out = gated @ W2 + b2, [4096, 1024]
    gemm_kernel<<<dim3(HIDDEN / 64, MTOT / 64), 256>>>(gated_p, W2, b2, out,
                                                       HIDDEN, HIDDEN, 0);
}

// round 2
// speedup vs baseline: 1.2814x; 1.2814x over previous
#include <cuda_runtime.h>

#define HIDDEN 1024
#define FOURH  4096
#define HEADS  16
#define HD     64
#define SEQ    2048
#define BATCH  2
#define MTOT   (BATCH * SEQ)   // 4096
#define MAXSEQ 2048

// Scratch (allocation-free rule: __device__ globals)
__device__ float g_act[(size_t)MTOT * FOURH];    // silu(x@W1+b1): [4096, 4096]
__device__ float g_gated[(size_t)MTOT * HIDDEN]; // attn_out * U : [4096, 1024]

__device__ __forceinline__ float silu_f(float x) {
    return __fdividef(x, 1.0f + __expf(-x));
}

// ---------------------------------------------------------------------------
// fp32 GEMM: C[M,N] = A[M,K] @ B[K,N] + bias[N], optional SiLU.
// 128x128 block tile, BK=8, 256 threads, 8x8 per thread (4 quads of 4x4),
// double-buffered shared memory with register prefetch.
// ---------------------------------------------------------------------------
__global__ __launch_bounds__(256, 2) void gemm_kernel(
    const float* __restrict__ A, const float* __restrict__ B,
    const float* __restrict__ bias, float* __restrict__ C,
    int N, int K, int do_silu)
{
    __shared__ float As[2][8][128];   // As[buf][k][m] (A transposed)
    __shared__ float Bs[2][8][128];   // Bs[buf][k][n]

    const int tid = threadIdx.x;
    const int tx  = tid & 15;         // n quad index
    const int ty  = tid >> 4;         // m quad index
    const int m0  = blockIdx.y << 7;
    const int n0  = blockIdx.x << 7;

    // A tile load map: 128 rows x 8 k, 1 float4 per thread
    const int ar = tid >> 1;          // 0..127
    const int ak = (tid & 1) << 2;    // 0 or 4
    // B tile load map: 8 k rows x 128 n, 1 float4 per thread
    const int br = tid >> 5;          // 0..7
    const int bc = (tid & 31) << 2;   // 0..124

    const float* Ap = A + (size_t)(m0 + ar) * K + ak;
    const float* Bp = B + (size_t)br * N + n0 + bc;

    float4 a_reg = *(const float4*)Ap;
    float4 b_reg = *(const float4*)Bp;
    As[0][ak + 0][ar] = a_reg.x;
    As[0][ak + 1][ar] = a_reg.y;
    As[0][ak + 2][ar] = a_reg.z;
    As[0][ak + 3][ar] = a_reg.w;
    *(float4*)&Bs[0][br][bc] = b_reg;
    __syncthreads();

    float acc[8][8] = {};
    int buf = 0;
    const int nstage = K >> 3;

    for (int s = 0; s < nstage; s++) {
        if (s + 1 < nstage) {
            int k0 = (s + 1) << 3;
            a_reg = *(const float4*)(Ap + k0);
            b_reg = *(const float4*)(Bp + (size_t)k0 * N);
        }
        #pragma unroll
        for (int kk = 0; kk < 8; kk++) {
            float4 a0 = *(const float4*)&As[buf][kk][ty << 2];
            float4 a1 = *(const float4*)&As[buf][kk][64 + (ty << 2)];
            float4 b0 = *(const float4*)&Bs[buf][kk][tx << 2];
            float4 b1 = *(const float4*)&Bs[buf][kk][64 + (tx << 2)];
            float am[8] = {a0.x, a0.y, a0.z, a0.w, a1.x, a1.y, a1.z, a1.w};
            float bn[8] = {b0.x, b0.y, b0.z, b0.w, b1.x, b1.y, b1.z, b1.w};
            #pragma unroll
            for (int i = 0; i < 8; i++)
                #pragma unroll
                for (int j = 0; j < 8; j++)
                    acc[i][j] += am[i] * bn[j];
        }
        if (s + 1 < nstage) {
            buf ^= 1;
            As[buf][ak + 0][ar] = a_reg.x;
            As[buf][ak + 1][ar] = a_reg.y;
            As[buf][ak + 2][ar] = a_reg.z;
            As[buf][ak + 3][ar] = a_reg.w;
            *(float4*)&Bs[buf][br][bc] = b_reg;
            __syncthreads();
        }
    }

    // Epilogue: bias + optional silu, 4 quads of 4x4
    const int cn0 = n0 + (tx << 2);
    float4 bb[2];
    bb[0] = *(const float4*)&bias[cn0];
    bb[1] = *(const float4*)&bias[cn0 + 64];
    #pragma unroll
    for (int hm = 0; hm < 2; hm++) {
        #pragma unroll
        for (int i = 0; i < 4; i++) {
            int row = m0 + hm * 64 + (ty << 2) + i;
            #pragma unroll
            for (int hn = 0; hn < 2; hn++) {
                float4 r;
                r.x = acc[hm * 4 + i][hn * 4 + 0] + bb[hn].x;
                r.y = acc[hm * 4 + i][hn * 4 + 1] + bb[hn].y;
                r.z = acc[hm * 4 + i][hn * 4 + 2] + bb[hn].z;
                r.w = acc[hm * 4 + i][hn * 4 + 3] + bb[hn].w;
                if (do_silu) {
                    r.x = silu_f(r.x); r.y = silu_f(r.y);
                    r.z = silu_f(r.z); r.w = silu_f(r.w);
                }
                *(float4*)&C[(size_t)row * N + cn0 + hn * 64] = r;
            }
        }
    }
}

// ---------------------------------------------------------------------------
// Fused HSTU attention. Per (b, head, q-tile of 128), causal loop over
// k-tiles of 64. 256 threads, 8x4 micro-tile.
//   S = silu(Q K^T * scale + rel_bias), causal-masked; out += S @ V;
//   gated = out * U  -> g_gated.
// Rel-bias: only 191 distinct (q-k) values per tile pair -> smem table.
// S stored TRANSPOSED (St[k][q]) via aligned STS.128 so the S@V loop is
// 3x LDS.128 per 32 FFMA (same intensity as the QK loop).
// Dynamic smem (floats): Qt[64][132] | St[64][132] | Kt[64][68] | Vs[64][68]
//                        | bias[192]  = 25792 floats = 103168 B.
// ---------------------------------------------------------------------------
#define ATTN_SMEM_FLOATS (64 * 132 * 2 + 64 * 68 * 2 + 192)

__global__ __launch_bounds__(256, 2) void attn_kernel(const float* __restrict__ rel_table)
{
    const int qt = gridDim.x - 1 - blockIdx.x;  // long tiles first
    const int h  = blockIdx.y;
    const int b  = blockIdx.z;

    extern __shared__ float sm[];
    float* Qt      = sm;                        // [64][132]  Qt[d][qi]
    float* St      = sm + 64 * 132;             // [64][132]  St[kj][qi]
    float* Kt      = sm + 2 * 64 * 132;         // [64][68]   Kt[d][kj]
    float* Vs      = Kt + 64 * 68;              // [64][68]   Vs[kj][d]
    float* bias_sm = Vs + 64 * 68;              // [192]

    const int tid = threadIdx.x;
    const int tx4 = (tid & 15) << 2;            // k-col / d-col quad
    const int ty4 = (tid >> 4) << 2;            // q-row quad (plus +64 half)
    const float scale = 0.125f;

    // ---- load Q tile (128 x 64), transposed into Qt[d][qi] ----
    {
        const int lrow = tid >> 1;              // 0..127
        const int lc   = (tid & 1) << 5;        // 0 or 32
        const float* src = g_act + (size_t)(b * SEQ + qt * 128 + lrow) * FOURH
                           + HIDDEN + h * HD + lc;
        #pragma unroll
        for (int u = 0; u < 8; u++) {
            float4 v = *(const float4*)(src + 4 * u);
            int c = lc + 4 * u;
            Qt[(c + 0) * 132 + lrow] = v.x;
            Qt[(c + 1) * 132 + lrow] = v.y;
            Qt[(c + 2) * 132 + lrow] = v.z;
            Qt[(c + 3) * 132 + lrow] = v.w;
        }
    }

    float acc[8][4] = {};
    const int kt_max = 2 * qt + 1;

    for (int kt = 0; kt <= kt_max; kt++) {
        __syncthreads();  // prev iter fully done with Kt/Vs/St (and Qt stores, iter 0)

        // ---- load K (transposed) and V tiles (64 x 64) + bias table ----
        {
            const int krow = tid >> 2;          // 0..63
            const int kc   = (tid & 3) << 4;    // 0,16,32,48
            const float* ksrc = g_act + (size_t)(b * SEQ + kt * 64 + krow) * FOURH
                                + 2 * HIDDEN + h * HD + kc;
            const float* vsrc = ksrc + HIDDEN;
            #pragma unroll
            for (int u = 0; u < 4; u++) {
                float4 kv = *(const float4*)(ksrc + 4 * u);
                int c = kc + 4 * u;
                Kt[(c + 0) * 68 + krow] = kv.x;
                Kt[(c + 1) * 68 + krow] = kv.y;
                Kt[(c + 2) * 68 + krow] = kv.z;
                Kt[(c + 3) * 68 + krow] = kv.w;
                *(float4*)&Vs[krow * 68 + c] = *(const float4*)(vsrc + 4 * u);
            }
            if (tid < 191) {
                int delta = qt * 128 - kt * 64 - 63 + tid;   // q - k
                bias_sm[tid] = rel_table[(size_t)(delta + MAXSEQ - 1) * HEADS + h];
            }
        }
        __syncthreads();

        // ---- s[8][4] = Q K^T ----
        float s[8][4] = {};
        #pragma unroll 4
        for (int d = 0; d < 64; d++) {
            float4 q0 = *(const float4*)&Qt[d * 132 + ty4];
            float4 q1 = *(const float4*)&Qt[d * 132 + 64 + ty4];
            float4 k4 = *(const float4*)&Kt[d * 68 + tx4];
            float qm[8] = {q0.x, q0.y, q0.z, q0.w, q1.x, q1.y, q1.z, q1.w};
            #pragma unroll
            for (int i = 0; i < 8; i++) {
                s[i][0] += qm[i] * k4.x;
                s[i][1] += qm[i] * k4.y;
                s[i][2] += qm[i] * k4.z;
                s[i][3] += qm[i] * k4.w;
            }
        }

        // ---- bias + silu + causal mask ----
        #pragma unroll
        for (int i = 0; i < 8; i++) {
            int row = (i < 4) ? (ty4 + i) : (64 + ty4 + i - 4);
            int qg  = qt * 128 + row;
            #pragma unroll
            for (int j = 0; j < 4; j++) {
                int col = tx4 + j;
                int kg  = kt * 64 + col;
                float v = silu_f(s[i][j] * scale + bias_sm[row - col + 63]);
                s[i][j] = (kg <= qg) ? v : 0.0f;
            }
        }

        // ---- store S transposed: St[col][row] via float4 of row-quads ----
        #pragma unroll
        for (int j = 0; j < 4; j++) {
            float4 r0 = make_float4(s[0][j], s[1][j], s[2][j], s[3][j]);
            float4 r1 = make_float4(s[4][j], s[5][j], s[6][j], s[7][j]);
            *(float4*)&St[(tx4 + j) * 132 + ty4]      = r0;
            *(float4*)&St[(tx4 + j) * 132 + 64 + ty4] = r1;
        }
        __syncthreads();

        // ---- out += S @ V  (reads St + Vs, 3 LDS.128 / 32 FFMA) ----
        #pragma unroll 4
        for (int kj = 0; kj < 64; kj++) {
            float4 s0 = *(const float4*)&St[kj * 132 + ty4];
            float4 s1 = *(const float4*)&St[kj * 132 + 64 + ty4];
            float4 v4 = *(const float4*)&Vs[kj * 68 + tx4];
            float sv[8] = {s0.x, s0.y, s0.z, s0.w, s1.x, s1.y, s1.z, s1.w};
            #pragma unroll
            for (int i = 0; i < 8; i++) {
                acc[i][0] += sv[i] * v4.x;
                acc[i][1] += sv[i] * v4.y;
                acc[i][2] += sv[i] * v4.z;
                acc[i][3] += sv[i] * v4.w;
            }
        }
    }

    // ---- epilogue: gated = out * U ----
    #pragma unroll
    for (int i = 0; i < 8; i++) {
        int row_loc = (i < 4) ? (ty4 + i) : (64 + ty4 + i - 4);
        size_t row  = (size_t)(b * SEQ + qt * 128 + row_loc);
        float4 u4 = *(const float4*)&g_act[row * FOURH + h * HD + tx4];
        float4 r  = make_float4(acc[i][0] * u4.x, acc[i][1] * u4.y,
                                acc[i][2] * u4.z, acc[i][3] * u4.w);
        *(float4*)&g_gated[row * HIDDEN + h * HD + tx4] = r;
    }
}

// ---------------------------------------------------------------------------
// Launch: GEMM1+silu -> fused attention+gate -> GEMM2+bias
// Inputs: x, W1, b1, W2, b2, rel_table, attn_mask (ignored: always causal
// tril by construction; causality applied analytically).
// ---------------------------------------------------------------------------
extern "C" void kernel_launch(void* const* d_in, const int* in_sizes, int n_in,
                              void* d_out, int out_size)
{
    const float* x   = (const float*)d_in[0];
    const float* W1  = (const float*)d_in[1];
    const float* b1  = (const float*)d_in[2];
    const float* W2  = (const float*)d_in[3];
    const float* b2  = (const float*)d_in[4];
    const float* rel = (const float*)d_in[5];
    float* out = (float*)d_out;

    float* act_p = nullptr;
    float* gated_p = nullptr;
    cudaGetSymbolAddress((void**)&act_p, g_act);
    cudaGetSymbolAddress((void**)&gated_p, g_gated);

    const int smem_attn = ATTN_SMEM_FLOATS * (int)sizeof(float);  // 103168 B
    cudaFuncSetAttribute(attn_kernel, cudaFuncAttributeMaxDynamicSharedMemorySize,
                         smem_attn);

    // GEMM1: activated = silu(x @ W1 + b1), [4096, 4096]
    gemm_kernel<<<dim3(FOURH / 128, MTOT / 128), 256>>>(x, W1, b1, act_p,
                                                        FOURH, HIDDEN, 1);
    // Fused attention + gating -> g_gated [4096, 1024]
    attn_kernel<<<dim3(SEQ / 128, HEADS, BATCH), 256, smem_attn>>>(rel);
    // GEMM2: out = gated @ W2 + b2, [4096, 1024]
    gemm_kernel<<<dim3(HIDDEN / 128, MTOT / 128), 256>>>(gated_p, W2, b2, out,
                                                         HIDDEN, HIDDEN, 0);
}

// round 6
// speedup vs baseline: 1.6655x; 1.2998x over previous
#include <cuda_runtime.h>
#include <cuda_bf16.h>
#include <cstdint>

#define HIDDEN 1024
#define FOURH  4096
#define HEADS  16
#define HD     64
#define SEQ    2048
#define BATCH  2
#define MTOT   (BATCH * SEQ)   // 4096
#define MAXSEQ 2048

// ---------------------------------------------------------------------------
// Scratch (__device__ globals; allocation-free rule)
// ---------------------------------------------------------------------------
__device__ float g_act[(size_t)MTOT * FOURH];                         // silu(x@W1+b1)
__device__ __align__(16) __nv_bfloat16 g_xhi[(size_t)MTOT * HIDDEN];  // x split
__device__ __align__(16) __nv_bfloat16 g_xlo[(size_t)MTOT * HIDDEN];
__device__ __align__(16) __nv_bfloat16 g_w1hi[(size_t)FOURH * HIDDEN];// W1^T split
__device__ __align__(16) __nv_bfloat16 g_w1lo[(size_t)FOURH * HIDDEN];
__device__ __align__(16) __nv_bfloat16 g_w2hi[(size_t)HIDDEN * HIDDEN];
__device__ __align__(16) __nv_bfloat16 g_w2lo[(size_t)HIDDEN * HIDDEN];
__device__ __align__(16) __nv_bfloat16 g_ghi[(size_t)MTOT * HIDDEN];  // gated split
__device__ __align__(16) __nv_bfloat16 g_glo[(size_t)MTOT * HIDDEN];

__device__ __forceinline__ float silu_f(float x) {
    return __fdividef(x, 1.0f + __expf(-x));
}

__device__ __forceinline__ uint32_t s2u(const void* p) {
    uint32_t a;
    asm("{ .reg .u64 t; cvta.to.shared.u64 t, %1; cvt.u32.u64 %0, t; }"
        : "=r"(a) : "l"(p));
    return a;
}

#define CP_ASYNC16(sa, ga) \
    asm volatile("cp.async.cg.shared.global [%0], [%1], 16;" \
                 :: "r"(sa), "l"(ga) : "memory")
#define CP_COMMIT()  asm volatile("cp.async.commit_group;" ::: "memory")
#define CP_WAIT1()   asm volatile("cp.async.wait_group 1;" ::: "memory")
#define CP_WAIT0()   asm volatile("cp.async.wait_group 0;" ::: "memory")

#define LDSM4(r, addr) \
    asm volatile("ldmatrix.sync.aligned.m8n8.x4.shared.b16 {%0,%1,%2,%3}, [%4];" \
                 : "=r"((r)[0]), "=r"((r)[1]), "=r"((r)[2]), "=r"((r)[3]) \
                 : "r"(addr))

#define MMA16816(c, a, b0, b1) \
    asm volatile("mma.sync.aligned.m16n8k16.row.col.f32.bf16.bf16.f32 " \
                 "{%0,%1,%2,%3}, {%4,%5,%6,%7}, {%8,%9}, {%0,%1,%2,%3};" \
                 : "+f"((c)[0]), "+f"((c)[1]), "+f"((c)[2]), "+f"((c)[3]) \
                 : "r"((a)[0]), "r"((a)[1]), "r"((a)[2]), "r"((a)[3]), \
                   "r"(b0), "r"(b1))

// ---------------------------------------------------------------------------
// Conversion kernels
// ---------------------------------------------------------------------------
__global__ void split_kernel(const float* __restrict__ src,
                             __nv_bfloat16* __restrict__ hi,
                             __nv_bfloat16* __restrict__ lo, int n)
{
    int i = blockIdx.x * blockDim.x + threadIdx.x;
    if (i < n) {
        float v = src[i];
        __nv_bfloat16 h = __float2bfloat16(v);
        hi[i] = h;
        lo[i] = __float2bfloat16(v - __bfloat162float(h));
    }
}

// W [K, N] row-major -> W^T hi/lo [N, K]
__global__ void transpose_split(const float* __restrict__ W,
                                __nv_bfloat16* __restrict__ Thi,
                                __nv_bfloat16* __restrict__ Tlo, int K, int N)
{
    __shared__ float t[32][33];
    int tx = threadIdx.x, ty = threadIdx.y;
    int n0 = blockIdx.x * 32, k0 = blockIdx.y * 32;
    #pragma unroll
    for (int i = 0; i < 4; i++)
        t[ty + 8 * i][tx] = W[(size_t)(k0 + ty + 8 * i) * N + n0 + tx];
    __syncthreads();
    #pragma unroll
    for (int i = 0; i < 4; i++) {
        int n = ty + 8 * i;
        float v = t[tx][n];
        __nv_bfloat16 h = __float2bfloat16(v);
        size_t o = (size_t)(n0 + n) * K + k0 + tx;
        Thi[o] = h;
        Tlo[o] = __float2bfloat16(v - __bfloat162float(h));
    }
}

// ---------------------------------------------------------------------------
// mma.sync bf16 GEMM with 3-product fp32 emulation.
//   C[M,N] = (Ahi+Alo) @ (Bhi+Blo)^T + bias  (lo*lo dropped), optional SiLU.
// A hi/lo [M,K] row-major bf16; BT hi/lo [N,K] row-major bf16.
// CTA tile 128x128, BK=32, 8 warps (2M x 4N, warp tile 64x32).
// Smem: pitch-80B rows (conflict-free ldmatrix), 2-stage cp.async pipeline.
// Stage layout: 4 arrays (Ah, Al, Bh, Bl), each 128 rows x 80B = 10240 B.
// ---------------------------------------------------------------------------
#define STAGE_BYTES (4 * 128 * 80)          // 40960
#define GEMM_SMEM   (2 * STAGE_BYTES)       // 81920

__global__ __launch_bounds__(256, 1) void mma_gemm(
    const __nv_bfloat16* __restrict__ Ahi, const __nv_bfloat16* __restrict__ Alo,
    const __nv_bfloat16* __restrict__ BThi, const __nv_bfloat16* __restrict__ BTlo,
    const float* __restrict__ bias, float* __restrict__ C,
    int N, int K, int do_silu)
{
    extern __shared__ __align__(128) char sm_raw[];
    const uint32_t sbase = s2u(sm_raw);

    const int tid = threadIdx.x;
    const int m0 = blockIdx.y << 7;
    const int n0 = blockIdx.x << 7;

    const __nv_bfloat16* gsrc[4] = {
        Ahi + (size_t)m0 * K, Alo + (size_t)m0 * K,
        BThi + (size_t)n0 * K, BTlo + (size_t)n0 * K };

    // load mapping: per array, 512 16B-chunks (128 rows x 4); 2 per thread
    const int lr = tid >> 2;         // 0..63  (row; second chunk at row+64)
    const int lc = tid & 3;          // 0..3   (16B chunk within 64B row)

    // mma operand addressing
    const int wid = tid >> 5, l = tid & 31;
    const int wm = wid >> 2;         // 0..1
    const int wn = wid & 3;          // 0..3
    const uint32_t offA = (uint32_t)((wm * 64 + ((l >> 3) & 1) * 8 + (l & 7)) * 80
                                     + (l >> 4) * 16);
    const uint32_t offB = (uint32_t)((wn * 32 + (l >> 4) * 8 + (l & 7)) * 80
                                     + ((l >> 3) & 1) * 16);

    float acc[4][4][4] = {};
    const int NS = K >> 5;

    // prologue: stage 0
    {
        const uint32_t sb = sbase;
        #pragma unroll
        for (int t = 0; t < 4; t++) {
            const __nv_bfloat16* g = gsrc[t] + lc * 8;
            uint32_t sa = sb + t * 10240 + lr * 80 + lc * 16;
            CP_ASYNC16(sa, g + (size_t)lr * K);
            CP_ASYNC16(sa + 64 * 80, g + (size_t)(lr + 64) * K);
        }
        CP_COMMIT();
    }

    for (int s = 0; s < NS; s++) {
        if (s + 1 < NS) {
            const int k0 = (s + 1) << 5;
            const uint32_t sb = sbase + ((s + 1) & 1) * STAGE_BYTES;
            #pragma unroll
            for (int t = 0; t < 4; t++) {
                const __nv_bfloat16* g = gsrc[t] + k0 + lc * 8;
                uint32_t sa = sb + t * 10240 + lr * 80 + lc * 16;
                CP_ASYNC16(sa, g + (size_t)lr * K);
                CP_ASYNC16(sa + 64 * 80, g + (size_t)(lr + 64) * K);
            }
            CP_COMMIT();
            CP_WAIT1();
        } else {
            CP_WAIT0();
        }
        __syncthreads();

        const uint32_t sb = sbase + (s & 1) * STAGE_BYTES;
        const uint32_t aH = sb, aL = sb + 10240, bH = sb + 20480, bL = sb + 30720;

        #pragma unroll
        for (int ks = 0; ks < 2; ks++) {
            uint32_t fa_h[4][4], fa_l[4][4];
            #pragma unroll
            for (int mt = 0; mt < 4; mt++) {
                LDSM4(fa_h[mt], aH + offA + mt * (16 * 80) + ks * 32);
                LDSM4(fa_l[mt], aL + offA + mt * (16 * 80) + ks * 32);
            }
            uint32_t fb_h[4][2], fb_l[4][2];
            #pragma unroll
            for (int np = 0; np < 2; np++) {
                uint32_t r[4];
                LDSM4(r, bH + offB + np * (16 * 80) + ks * 32);
                fb_h[np * 2][0] = r[0]; fb_h[np * 2][1] = r[1];
                fb_h[np * 2 + 1][0] = r[2]; fb_h[np * 2 + 1][1] = r[3];
                LDSM4(r, bL + offB + np * (16 * 80) + ks * 32);
                fb_l[np * 2][0] = r[0]; fb_l[np * 2][1] = r[1];
                fb_l[np * 2 + 1][0] = r[2]; fb_l[np * 2 + 1][1] = r[3];
            }
            #pragma unroll
            for (int mt = 0; mt < 4; mt++)
                #pragma unroll
                for (int nt = 0; nt < 4; nt++) {
                    MMA16816(acc[mt][nt], fa_h[mt], fb_h[nt][0], fb_h[nt][1]);
                    MMA16816(acc[mt][nt], fa_h[mt], fb_l[nt][0], fb_l[nt][1]);
                    MMA16816(acc[mt][nt], fa_l[mt], fb_h[nt][0], fb_h[nt][1]);
                }
        }
        __syncthreads();
    }

    // epilogue: bias + optional silu, direct stores
    const int rbase = m0 + wm * 64 + (l >> 2);
    const int cbase = n0 + wn * 32 + (l & 3) * 2;
    #pragma unroll
    for (int nt = 0; nt < 4; nt++) {
        const int col = cbase + nt * 8;
        const float bx = bias[col], by = bias[col + 1];
        #pragma unroll
        for (int mt = 0; mt < 4; mt++) {
            #pragma unroll
            for (int half = 0; half < 2; half++) {
                const int row = rbase + mt * 16 + half * 8;
                float v0 = acc[mt][nt][half * 2 + 0] + bx;
                float v1 = acc[mt][nt][half * 2 + 1] + by;
                if (do_silu) { v0 = silu_f(v0); v1 = silu_f(v1); }
                float2 r = make_float2(v0, v1);
                *(float2*)&C[(size_t)row * N + col] = r;
            }
        }
    }
}

// ---------------------------------------------------------------------------
// Fused HSTU attention (round-2 kernel; epilogue writes bf16 hi/lo split).
// ---------------------------------------------------------------------------
#define ATTN_SMEM_FLOATS (64 * 132 * 2 + 64 * 68 * 2 + 192)

__global__ __launch_bounds__(256, 2) void attn_kernel(const float* __restrict__ rel_table)
{
    const int qt = gridDim.x - 1 - blockIdx.x;  // long tiles first
    const int h  = blockIdx.y;
    const int b  = blockIdx.z;

    extern __shared__ float sm[];
    float* Qt      = sm;                        // [64][132]  Qt[d][qi]
    float* St      = sm + 64 * 132;             // [64][132]  St[kj][qi]
    float* Kt      = sm + 2 * 64 * 132;         // [64][68]   Kt[d][kj]
    float* Vs      = Kt + 64 * 68;              // [64][68]   Vs[kj][d]
    float* bias_sm = Vs + 64 * 68;              // [192]

    const int tid = threadIdx.x;
    const int tx4 = (tid & 15) << 2;
    const int ty4 = (tid >> 4) << 2;
    const float scale = 0.125f;

    {
        const int lrow = tid >> 1;
        const int lc   = (tid & 1) << 5;
        const float* src = g_act + (size_t)(b * SEQ + qt * 128 + lrow) * FOURH
                           + HIDDEN + h * HD + lc;
        #pragma unroll
        for (int u = 0; u < 8; u++) {
            float4 v = *(const float4*)(src + 4 * u);
            int c = lc + 4 * u;
            Qt[(c + 0) * 132 + lrow] = v.x;
            Qt[(c + 1) * 132 + lrow] = v.y;
            Qt[(c + 2) * 132 + lrow] = v.z;
            Qt[(c + 3) * 132 + lrow] = v.w;
        }
    }

    float acc[8][4] = {};
    const int kt_max = 2 * qt + 1;

    for (int kt = 0; kt <= kt_max; kt++) {
        __syncthreads();
        {
            const int krow = tid >> 2;
            const int kc   = (tid & 3) << 4;
            const float* ksrc = g_act + (size_t)(b * SEQ + kt * 64 + krow) * FOURH
                                + 2 * HIDDEN + h * HD + kc;
            const float* vsrc = ksrc + HIDDEN;
            #pragma unroll
            for (int u = 0; u < 4; u++) {
                float4 kv = *(const float4*)(ksrc + 4 * u);
                int c = kc + 4 * u;
                Kt[(c + 0) * 68 + krow] = kv.x;
                Kt[(c + 1) * 68 + krow] = kv.y;
                Kt[(c + 2) * 68 + krow] = kv.z;
                Kt[(c + 3) * 68 + krow] = kv.w;
                *(float4*)&Vs[krow * 68 + c] = *(const float4*)(vsrc + 4 * u);
            }
            if (tid < 191) {
                int delta = qt * 128 - kt * 64 - 63 + tid;
                bias_sm[tid] = rel_table[(size_t)(delta + MAXSEQ - 1) * HEADS + h];
            }
        }
        __syncthreads();

        float s[8][4] = {};
        #pragma unroll 4
        for (int d = 0; d < 64; d++) {
            float4 q0 = *(const float4*)&Qt[d * 132 + ty4];
            float4 q1 = *(const float4*)&Qt[d * 132 + 64 + ty4];
            float4 k4 = *(const float4*)&Kt[d * 68 + tx4];
            float qm[8] = {q0.x, q0.y, q0.z, q0.w, q1.x, q1.y, q1.z, q1.w};
            #pragma unroll
            for (int i = 0; i < 8; i++) {
                s[i][0] += qm[i] * k4.x;
                s[i][1] += qm[i] * k4.y;
                s[i][2] += qm[i] * k4.z;
                s[i][3] += qm[i] * k4.w;
            }
        }

        #pragma unroll
        for (int i = 0; i < 8; i++) {
            int row = (i < 4) ? (ty4 + i) : (64 + ty4 + i - 4);
            int qg  = qt * 128 + row;
            #pragma unroll
            for (int j = 0; j < 4; j++) {
                int col = tx4 + j;
                int kg  = kt * 64 + col;
                float v = silu_f(s[i][j] * scale + bias_sm[row - col + 63]);
                s[i][j] = (kg <= qg) ? v : 0.0f;
            }
        }

        __syncthreads();
        #pragma unroll
        for (int j = 0; j < 4; j++) {
            float4 r0 = make_float4(s[0][j], s[1][j], s[2][j], s[3][j]);
            float4 r1 = make_float4(s[4][j], s[5][j], s[6][j], s[7][j]);
            *(float4*)&St[(tx4 + j) * 132 + ty4]      = r0;
            *(float4*)&St[(tx4 + j) * 132 + 64 + ty4] = r1;
        }
        __syncthreads();

        #pragma unroll 4
        for (int kj = 0; kj < 64; kj++) {
            float4 s0 = *(const float4*)&St[kj * 132 + ty4];
            float4 s1 = *(const float4*)&St[kj * 132 + 64 + ty4];
            float4 v4 = *(const float4*)&Vs[kj * 68 + tx4];
            float sv[8] = {s0.x, s0.y, s0.z, s0.w, s1.x, s1.y, s1.z, s1.w};
            #pragma unroll
            for (int i = 0; i < 8; i++) {
                acc[i][0] += sv[i] * v4.x;
                acc[i][1] += sv[i] * v4.y;
                acc[i][2] += sv[i] * v4.z;
                acc[i][3] += sv[i] * v4.w;
            }
        }
    }

    // Epilogue: gated = out * U, split into bf16 hi/lo for GEMM2
    #pragma unroll
    for (int i = 0; i < 8; i++) {
        int row_loc = (i < 4) ? (ty4 + i) : (64 + ty4 + i - 4);
        size_t row  = (size_t)(b * SEQ + qt * 128 + row_loc);
        float4 u4 = *(const float4*)&g_act[row * FOURH + h * HD + tx4];
        float4 r  = make_float4(acc[i][0] * u4.x, acc[i][1] * u4.y,
                                acc[i][2] * u4.z, acc[i][3] * u4.w);
        __nv_bfloat162 h01, h23, l01, l23;
        h01.x = __float2bfloat16(r.x);
        h01.y = __float2bfloat16(r.y);
        h23.x = __float2bfloat16(r.z);
        h23.y = __float2bfloat16(r.w);
        l01.x = __float2bfloat16(r.x - __bfloat162float(h01.x));
        l01.y = __float2bfloat16(r.y - __bfloat162float(h01.y));
        l23.x = __float2bfloat16(r.z - __bfloat162float(h23.x));
        l23.y = __float2bfloat16(r.w - __bfloat162float(h23.y));
        size_t o = row * HIDDEN + h * HD + tx4;
        *(__nv_bfloat162*)&g_ghi[o]     = h01;
        *(__nv_bfloat162*)&g_ghi[o + 2] = h23;
        *(__nv_bfloat162*)&g_glo[o]     = l01;
        *(__nv_bfloat162*)&g_glo[o + 2] = l23;
    }
}

// ---------------------------------------------------------------------------
// Launch. Inputs: x, W1, b1, W2, b2, rel_table, attn_mask (ignored: always
// the causal tril by construction; causality applied analytically).
// ---------------------------------------------------------------------------
extern "C" void kernel_launch(void* const* d_in, const int* in_sizes, int n_in,
                              void* d_out, int out_size)
{
    const float* x   = (const float*)d_in[0];
    const float* W1  = (const float*)d_in[1];
    const float* b1  = (const float*)d_in[2];
    const float* W2  = (const float*)d_in[3];
    const float* b2  = (const float*)d_in[4];
    const float* rel = (const float*)d_in[5];
    float* out = (float*)d_out;

    float *act_p;
    __nv_bfloat16 *xhi, *xlo, *w1hi, *w1lo, *w2hi, *w2lo, *ghi, *glo;
    cudaGetSymbolAddress((void**)&act_p, g_act);
    cudaGetSymbolAddress((void**)&xhi, g_xhi);
    cudaGetSymbolAddress((void**)&xlo, g_xlo);
    cudaGetSymbolAddress((void**)&w1hi, g_w1hi);
    cudaGetSymbolAddress((void**)&w1lo, g_w1lo);
    cudaGetSymbolAddress((void**)&w2hi, g_w2hi);
    cudaGetSymbolAddress((void**)&w2lo, g_w2lo);
    cudaGetSymbolAddress((void**)&ghi, g_ghi);
    cudaGetSymbolAddress((void**)&glo, g_glo);

    cudaFuncSetAttribute(mma_gemm, cudaFuncAttributeMaxDynamicSharedMemorySize,
                         GEMM_SMEM);
    const int smem_attn = ATTN_SMEM_FLOATS * (int)sizeof(float);
    cudaFuncSetAttribute(attn_kernel, cudaFuncAttributeMaxDynamicSharedMemorySize,
                         smem_attn);

    // Split/transpose conversions
    split_kernel<<<(MTOT * HIDDEN) / 256, 256>>>(x, xhi, xlo, MTOT * HIDDEN);
    transpose_split<<<dim3(FOURH / 32, HIDDEN / 32), dim3(32, 8)>>>(W1, w1hi, w1lo,
                                                                    HIDDEN, FOURH);
    transpose_split<<<dim3(HIDDEN / 32, HIDDEN / 32), dim3(32, 8)>>>(W2, w2hi, w2lo,
                                                                     HIDDEN, HIDDEN);
    // GEMM1: activated = silu(x @ W1 + b1)  [4096, 4096]
    mma_gemm<<<dim3(FOURH / 128, MTOT / 128), 256, GEMM_SMEM>>>(
        xhi, xlo, w1hi, w1lo, b1, act_p, FOURH, HIDDEN, 1);
    // Fused attention + gating -> g_ghi/g_glo
    attn_kernel<<<dim3(SEQ / 128, HEADS, BATCH), 256, smem_attn>>>(rel);
    // GEMM2: out = gated @ W2 + b2  [4096, 1024]
    mma_gemm<<<dim3(HIDDEN / 128, MTOT / 128), 256, GEMM_SMEM>>>(
        ghi, glo, w2hi, w2lo, b2, out, HIDDEN, HIDDEN, 0);
}

// round 7
// speedup vs baseline: 2.4941x; 1.4975x over previous
#include <cuda_runtime.h>
#include <cuda_bf16.h>
#include <cstdint>

#define HIDDEN 1024
#define FOURH  4096
#define HEADS  16
#define HD     64
#define SEQ    2048
#define BATCH  2
#define MTOT   (BATCH * SEQ)   // 4096
#define MAXSEQ 2048

// ---------------------------------------------------------------------------
// Scratch (__device__ globals; allocation-free rule)
// ---------------------------------------------------------------------------
__device__ float g_act[(size_t)MTOT * FOURH];                          // silu(x@W1+b1) fp32
__device__ __align__(16) __nv_bfloat16 g_acthi[(size_t)MTOT * FOURH];  // act split
__device__ __align__(16) __nv_bfloat16 g_actlo[(size_t)MTOT * FOURH];
__device__ __align__(16) __nv_bfloat16 g_xhi[(size_t)MTOT * HIDDEN];   // x split
__device__ __align__(16) __nv_bfloat16 g_xlo[(size_t)MTOT * HIDDEN];
__device__ __align__(16) __nv_bfloat16 g_w1hi[(size_t)FOURH * HIDDEN]; // W1^T split
__device__ __align__(16) __nv_bfloat16 g_w1lo[(size_t)FOURH * HIDDEN];
__device__ __align__(16) __nv_bfloat16 g_w2hi[(size_t)HIDDEN * HIDDEN];
__device__ __align__(16) __nv_bfloat16 g_w2lo[(size_t)HIDDEN * HIDDEN];
__device__ __align__(16) __nv_bfloat16 g_vthi[(size_t)BATCH * HIDDEN * SEQ]; // V^T [b,h,d,s]
__device__ __align__(16) __nv_bfloat16 g_vtlo[(size_t)BATCH * HIDDEN * SEQ];
__device__ __align__(16) __nv_bfloat16 g_ghi[(size_t)MTOT * HIDDEN];   // gated split
__device__ __align__(16) __nv_bfloat16 g_glo[(size_t)MTOT * HIDDEN];

__device__ __forceinline__ float silu_f(float x) {
    return __fdividef(x, 1.0f + __expf(-x));
}

__device__ __forceinline__ uint32_t s2u(const void* p) {
    uint32_t a;
    asm("{ .reg .u64 t; cvta.to.shared.u64 t, %1; cvt.u32.u64 %0, t; }"
        : "=r"(a) : "l"(p));
    return a;
}

#define CP_ASYNC16(sa, ga) \
    asm volatile("cp.async.cg.shared.global [%0], [%1], 16;" \
                 :: "r"(sa), "l"(ga) : "memory")
#define CP_COMMIT()  asm volatile("cp.async.commit_group;" ::: "memory")
#define CP_WAIT1()   asm volatile("cp.async.wait_group 1;" ::: "memory")
#define CP_WAIT0()   asm volatile("cp.async.wait_group 0;" ::: "memory")

#define LDSM4(r, addr) \
    asm volatile("ldmatrix.sync.aligned.m8n8.x4.shared.b16 {%0,%1,%2,%3}, [%4];" \
                 : "=r"((r)[0]), "=r"((r)[1]), "=r"((r)[2]), "=r"((r)[3]) \
                 : "r"(addr))

#define MMA16816(c, a, b0, b1) \
    asm volatile("mma.sync.aligned.m16n8k16.row.col.f32.bf16.bf16.f32 " \
                 "{%0,%1,%2,%3}, {%4,%5,%6,%7}, {%8,%9}, {%0,%1,%2,%3};" \
                 : "+f"((c)[0]), "+f"((c)[1]), "+f"((c)[2]), "+f"((c)[3]) \
                 : "r"((a)[0]), "r"((a)[1]), "r"((a)[2]), "r"((a)[3]), \
                   "r"(b0), "r"(b1))

__device__ __forceinline__ uint32_t pack_bf2(__nv_bfloat16 lo, __nv_bfloat16 hi) {
    __nv_bfloat162 t(lo, hi);                 // .x = low = even col, .y = odd col
    return *(uint32_t*)&t;
}

// ---------------------------------------------------------------------------
// Conversion kernels
// ---------------------------------------------------------------------------
__global__ void split_kernel(const float* __restrict__ src,
                             __nv_bfloat16* __restrict__ hi,
                             __nv_bfloat16* __restrict__ lo, int n)
{
    int i = blockIdx.x * blockDim.x + threadIdx.x;
    if (i < n) {
        float v = src[i];
        __nv_bfloat16 h = __float2bfloat16(v);
        hi[i] = h;
        lo[i] = __float2bfloat16(v - __bfloat162float(h));
    }
}

// W [K, N] row-major -> W^T hi/lo [N, K]
__global__ void transpose_split(const float* __restrict__ W,
                                __nv_bfloat16* __restrict__ Thi,
                                __nv_bfloat16* __restrict__ Tlo, int K, int N)
{
    __shared__ float t[32][33];
    int tx = threadIdx.x, ty = threadIdx.y;
    int n0 = blockIdx.x * 32, k0 = blockIdx.y * 32;
    #pragma unroll
    for (int i = 0; i < 4; i++)
        t[ty + 8 * i][tx] = W[(size_t)(k0 + ty + 8 * i) * N + n0 + tx];
    __syncthreads();
    #pragma unroll
    for (int i = 0; i < 4; i++) {
        int n = ty + 8 * i;
        float v = t[tx][n];
        __nv_bfloat16 h = __float2bfloat16(v);
        size_t o = (size_t)(n0 + n) * K + k0 + tx;
        Thi[o] = h;
        Tlo[o] = __float2bfloat16(v - __bfloat162float(h));
    }
}

// V region of g_act (cols 3072..4095) -> V^T hi/lo [b, h, d, s]
__global__ void v_transpose_split()
{
    __shared__ float t[32][33];
    int tx = threadIdx.x, ty = threadIdx.y;
    int s0 = blockIdx.x * 32, c0 = blockIdx.y * 32, b = blockIdx.z;
    #pragma unroll
    for (int i = 0; i < 4; i++)
        t[ty + 8 * i][tx] =
            g_act[(size_t)(b * SEQ + s0 + ty + 8 * i) * FOURH + 3 * HIDDEN + c0 + tx];
    __syncthreads();
    #pragma unroll
    for (int i = 0; i < 4; i++) {
        int cl = ty + 8 * i;
        int c = c0 + cl;
        int hh = c >> 6, d = c & 63;
        float v = t[tx][cl];
        __nv_bfloat16 h = __float2bfloat16(v);
        size_t o = (size_t)((b * HEADS + hh) * HD + d) * SEQ + s0 + tx;
        g_vthi[o] = h;
        g_vtlo[o] = __float2bfloat16(v - __bfloat162float(h));
    }
}

// ---------------------------------------------------------------------------
// mma.sync bf16 GEMM with 3-product fp32 emulation (round-6, validated).
// Optionally also writes bf16 hi/lo split of C (for downstream mma consumers).
// ---------------------------------------------------------------------------
#define STAGE_BYTES (4 * 128 * 80)          // 40960
#define GEMM_SMEM   (2 * STAGE_BYTES)       // 81920

__global__ __launch_bounds__(256, 1) void mma_gemm(
    const __nv_bfloat16* __restrict__ Ahi, const __nv_bfloat16* __restrict__ Alo,
    const __nv_bfloat16* __restrict__ BThi, const __nv_bfloat16* __restrict__ BTlo,
    const float* __restrict__ bias, float* __restrict__ C,
    __nv_bfloat16* __restrict__ Chi, __nv_bfloat16* __restrict__ Clo,
    int N, int K, int do_silu)
{
    extern __shared__ __align__(128) char sm_raw[];
    const uint32_t sbase = s2u(sm_raw);

    const int tid = threadIdx.x;
    const int m0 = blockIdx.y << 7;
    const int n0 = blockIdx.x << 7;

    const __nv_bfloat16* gsrc[4] = {
        Ahi + (size_t)m0 * K, Alo + (size_t)m0 * K,
        BThi + (size_t)n0 * K, BTlo + (size_t)n0 * K };

    const int lr = tid >> 2;
    const int lc = tid & 3;

    const int wid = tid >> 5, l = tid & 31;
    const int wm = wid >> 2;
    const int wn = wid & 3;
    const uint32_t offA = (uint32_t)((wm * 64 + ((l >> 3) & 1) * 8 + (l & 7)) * 80
                                     + (l >> 4) * 16);
    const uint32_t offB = (uint32_t)((wn * 32 + (l >> 4) * 8 + (l & 7)) * 80
                                     + ((l >> 3) & 1) * 16);

    float acc[4][4][4] = {};
    const int NS = K >> 5;

    {
        const uint32_t sb = sbase;
        #pragma unroll
        for (int t = 0; t < 4; t++) {
            const __nv_bfloat16* g = gsrc[t] + lc * 8;
            uint32_t sa = sb + t * 10240 + lr * 80 + lc * 16;
            CP_ASYNC16(sa, g + (size_t)lr * K);
            CP_ASYNC16(sa + 64 * 80, g + (size_t)(lr + 64) * K);
        }
        CP_COMMIT();
    }

    for (int s = 0; s < NS; s++) {
        if (s + 1 < NS) {
            const int k0 = (s + 1) << 5;
            const uint32_t sb = sbase + ((s + 1) & 1) * STAGE_BYTES;
            #pragma unroll
            for (int t = 0; t < 4; t++) {
                const __nv_bfloat16* g = gsrc[t] + k0 + lc * 8;
                uint32_t sa = sb + t * 10240 + lr * 80 + lc * 16;
                CP_ASYNC16(sa, g + (size_t)lr * K);
                CP_ASYNC16(sa + 64 * 80, g + (size_t)(lr + 64) * K);
            }
            CP_COMMIT();
            CP_WAIT1();
        } else {
            CP_WAIT0();
        }
        __syncthreads();

        const uint32_t sb = sbase + (s & 1) * STAGE_BYTES;
        const uint32_t aH = sb, aL = sb + 10240, bH = sb + 20480, bL = sb + 30720;

        #pragma unroll
        for (int ks = 0; ks < 2; ks++) {
            uint32_t fa_h[4][4], fa_l[4][4];
            #pragma unroll
            for (int mt = 0; mt < 4; mt++) {
                LDSM4(fa_h[mt], aH + offA + mt * (16 * 80) + ks * 32);
                LDSM4(fa_l[mt], aL + offA + mt * (16 * 80) + ks * 32);
            }
            uint32_t fb_h[4][2], fb_l[4][2];
            #pragma unroll
            for (int np = 0; np < 2; np++) {
                uint32_t r[4];
                LDSM4(r, bH + offB + np * (16 * 80) + ks * 32);
                fb_h[np * 2][0] = r[0]; fb_h[np * 2][1] = r[1];
                fb_h[np * 2 + 1][0] = r[2]; fb_h[np * 2 + 1][1] = r[3];
                LDSM4(r, bL + offB + np * (16 * 80) + ks * 32);
                fb_l[np * 2][0] = r[0]; fb_l[np * 2][1] = r[1];
                fb_l[np * 2 + 1][0] = r[2]; fb_l[np * 2 + 1][1] = r[3];
            }
            #pragma unroll
            for (int mt = 0; mt < 4; mt++)
                #pragma unroll
                for (int nt = 0; nt < 4; nt++) {
                    MMA16816(acc[mt][nt], fa_h[mt], fb_h[nt][0], fb_h[nt][1]);
                    MMA16816(acc[mt][nt], fa_h[mt], fb_l[nt][0], fb_l[nt][1]);
                    MMA16816(acc[mt][nt], fa_l[mt], fb_h[nt][0], fb_h[nt][1]);
                }
        }
        __syncthreads();
    }

    const int rbase = m0 + wm * 64 + (l >> 2);
    const int cbase = n0 + wn * 32 + (l & 3) * 2;
    #pragma unroll
    for (int nt = 0; nt < 4; nt++) {
        const int col = cbase + nt * 8;
        const float bx = bias[col], by = bias[col + 1];
        #pragma unroll
        for (int mt = 0; mt < 4; mt++) {
            #pragma unroll
            for (int half = 0; half < 2; half++) {
                const int row = rbase + mt * 16 + half * 8;
                float v0 = acc[mt][nt][half * 2 + 0] + bx;
                float v1 = acc[mt][nt][half * 2 + 1] + by;
                if (do_silu) { v0 = silu_f(v0); v1 = silu_f(v1); }
                *(float2*)&C[(size_t)row * N + col] = make_float2(v0, v1);
                if (Chi) {
                    __nv_bfloat16 h0 = __float2bfloat16(v0);
                    __nv_bfloat16 h1 = __float2bfloat16(v1);
                    __nv_bfloat16 l0 = __float2bfloat16(v0 - __bfloat162float(h0));
                    __nv_bfloat16 l1 = __float2bfloat16(v1 - __bfloat162float(h1));
                    *(uint32_t*)&Chi[(size_t)row * N + col] = pack_bf2(h0, h1);
                    *(uint32_t*)&Clo[(size_t)row * N + col] = pack_bf2(l0, l1);
                }
            }
        }
    }
}

// ---------------------------------------------------------------------------
// Tensor-core HSTU attention.
// CTA = (b, h, 128-q-tile); 8 warps x 16 q-rows. Causal loop over 64-k-tiles.
// QK^T and S@V via mma.sync bf16 3-product split; S lives only in registers
// (accum fragment == A fragment layout). K/V double-buffered via cp.async.
// smem stage: Khi|Klo|Vthi|Vtlo each [64][72] bf16 (pitch 144B, ldmatrix
// conflict-free since 9*16B rows). Q loaded via stage0 then held in regs.
// ---------------------------------------------------------------------------
#define AP     72                       // pitch in elements (144 B)
#define ST_KH  0
#define ST_KL  9216
#define ST_VH  18432
#define ST_VL  27648
#define ST_SZ  36864
#define ATTN_SMEM (2 * ST_SZ)           // 73728

__global__ __launch_bounds__(256) void attn_mma(const float* __restrict__ rel_table)
{
    const int qt = gridDim.x - 1 - blockIdx.x;  // long tiles first
    const int h  = blockIdx.y;
    const int b  = blockIdx.z;

    extern __shared__ __align__(128) char smraw[];
    const uint32_t sb0 = s2u(smraw);
    __shared__ float bias_s[192];

    const int tid = threadIdx.x;
    const int w = tid >> 5, l = tid & 31;

    // ---- Q tile (128 x 64 hi+lo) via cp.async into stage0 area ----
    {
        const int arr = tid >> 7;           // 0 = hi, 1 = lo
        const int u = tid & 127;
        const __nv_bfloat16* src = arr ? g_actlo : g_acthi;
        const uint32_t qb = sb0 + arr * 18432;
        #pragma unroll
        for (int i = 0; i < 8; i++) {
            int r = (u >> 3) + 16 * i;
            int c = u & 7;
            CP_ASYNC16(qb + r * 144 + c * 16,
                       src + (size_t)(b * SEQ + qt * 128 + r) * FOURH
                           + HIDDEN + h * HD + c * 8);
        }
        CP_COMMIT();
        CP_WAIT0();
    }
    __syncthreads();

    uint32_t qh[4][4], ql[4][4];
    #pragma unroll
    for (int kc = 0; kc < 4; kc++) {
        uint32_t a = sb0 + (uint32_t)((w * 16 + ((l >> 3) & 1) * 8 + (l & 7)) * AP
                                      + kc * 16 + (l >> 4) * 8) * 2;
        LDSM4(qh[kc], a);
        LDSM4(ql[kc], a + 18432);
    }
    __syncthreads();

    float oacc[8][4] = {};
    const int ktmax = 2 * qt + 1;

    // K/V stage loader: 4 arrays x 64 rows x 8 16B-chunks
    const int arr = tid >> 6;               // 0 Khi, 1 Klo, 2 Vthi, 3 Vtlo
    const int u = tid & 63;
    const size_t krow0 = (size_t)(b * SEQ) * FOURH + 2 * HIDDEN + h * HD;
    const size_t vrow0 = (size_t)((b * HEADS + h) * HD) * SEQ;

    #define ISSUE_STAGE(buf, ktv) do {                                         \
        const uint32_t base_ = sb0 + (buf) * ST_SZ + arr * 9216;               \
        _Pragma("unroll")                                                      \
        for (int i_ = 0; i_ < 8; i_++) {                                       \
            int r_ = (u >> 3) + 8 * i_;                                        \
            int c_ = u & 7;                                                    \
            const __nv_bfloat16* g_;                                           \
            if (arr == 0)                                                      \
                g_ = g_acthi + krow0 + (size_t)((ktv) * 64 + r_) * FOURH + c_ * 8; \
            else if (arr == 1)                                                 \
                g_ = g_actlo + krow0 + (size_t)((ktv) * 64 + r_) * FOURH + c_ * 8; \
            else if (arr == 2)                                                 \
                g_ = g_vthi + vrow0 + (size_t)r_ * SEQ + (ktv) * 64 + c_ * 8;  \
            else                                                               \
                g_ = g_vtlo + vrow0 + (size_t)r_ * SEQ + (ktv) * 64 + c_ * 8;  \
            CP_ASYNC16(base_ + r_ * 144 + c_ * 16, g_);                        \
        }                                                                      \
    } while (0)

    ISSUE_STAGE(0, 0);
    CP_COMMIT();

    for (int kt = 0; kt <= ktmax; kt++) {
        if (kt < ktmax) {
            ISSUE_STAGE((kt + 1) & 1, kt + 1);
            CP_COMMIT();
            CP_WAIT1();
        } else {
            CP_WAIT0();
        }
        if (tid < 191)
            bias_s[tid] = rel_table[(size_t)(qt * 128 - kt * 64 - 63 + tid
                                             + MAXSEQ - 1) * HEADS + h];
        __syncthreads();

        const uint32_t stg = sb0 + (kt & 1) * ST_SZ;
        const uint32_t offB = (uint32_t)(((l >> 4) * 8 + (l & 7)) * AP
                                         + ((l >> 3) & 1) * 8) * 2;

        // ---- S = Q K^T (3-product) ----
        float sacc[8][4] = {};
        #pragma unroll
        for (int kc = 0; kc < 4; kc++) {
            #pragma unroll
            for (int ntp = 0; ntp < 4; ntp++) {
                uint32_t addr = stg + offB + (uint32_t)(ntp * 16 * AP + kc * 16) * 2;
                uint32_t kh[4], kl[4];
                LDSM4(kh, addr + ST_KH);
                LDSM4(kl, addr + ST_KL);
                #pragma unroll
                for (int t = 0; t < 2; t++) {
                    int nt = ntp * 2 + t;
                    MMA16816(sacc[nt], qh[kc], kh[t * 2], kh[t * 2 + 1]);
                    MMA16816(sacc[nt], qh[kc], kl[t * 2], kl[t * 2 + 1]);
                    MMA16816(sacc[nt], ql[kc], kh[t * 2], kh[t * 2 + 1]);
                }
            }
        }

        // ---- scale + bias + silu + causal mask; split to bf16 hi/lo ----
        uint32_t shi[8][2], slo[8][2];
        #pragma unroll
        for (int nt = 0; nt < 8; nt++) {
            const int c0 = nt * 8 + (l & 3) * 2;
            const int r0 = w * 16 + (l >> 2);
            float vv[4];
            #pragma unroll
            for (int e = 0; e < 4; e++) {
                int rr = r0 + (e >> 1) * 8;
                int cc = c0 + (e & 1);
                float v = sacc[nt][e] * 0.125f + bias_s[rr - cc + 63];
                v = silu_f(v);
                vv[e] = ((kt * 64 + cc) <= (qt * 128 + rr)) ? v : 0.0f;
            }
            __nv_bfloat16 h0 = __float2bfloat16(vv[0]);
            __nv_bfloat16 h1 = __float2bfloat16(vv[1]);
            __nv_bfloat16 h2 = __float2bfloat16(vv[2]);
            __nv_bfloat16 h3 = __float2bfloat16(vv[3]);
            shi[nt][0] = pack_bf2(h0, h1);
            shi[nt][1] = pack_bf2(h2, h3);
            slo[nt][0] = pack_bf2(__float2bfloat16(vv[0] - __bfloat162float(h0)),
                                  __float2bfloat16(vv[1] - __bfloat162float(h1)));
            slo[nt][1] = pack_bf2(__float2bfloat16(vv[2] - __bfloat162float(h2)),
                                  __float2bfloat16(vv[3] - __bfloat162float(h3)));
        }

        // ---- out += S @ V (3-product; S accum frags reused as A frags) ----
        #pragma unroll
        for (int kc2 = 0; kc2 < 4; kc2++) {
            uint32_t ah[4] = { shi[2 * kc2][0], shi[2 * kc2][1],
                               shi[2 * kc2 + 1][0], shi[2 * kc2 + 1][1] };
            uint32_t al[4] = { slo[2 * kc2][0], slo[2 * kc2][1],
                               slo[2 * kc2 + 1][0], slo[2 * kc2 + 1][1] };
            #pragma unroll
            for (int ntp = 0; ntp < 4; ntp++) {
                uint32_t addr = stg + offB + (uint32_t)(ntp * 16 * AP + kc2 * 16) * 2;
                uint32_t vh[4], vl[4];
                LDSM4(vh, addr + ST_VH);
                LDSM4(vl, addr + ST_VL);
                #pragma unroll
                for (int t = 0; t < 2; t++) {
                    int nt = ntp * 2 + t;
                    MMA16816(oacc[nt], ah, vh[t * 2], vh[t * 2 + 1]);
                    MMA16816(oacc[nt], ah, vl[t * 2], vl[t * 2 + 1]);
                    MMA16816(oacc[nt], al, vh[t * 2], vh[t * 2 + 1]);
                }
            }
        }
        __syncthreads();
    }
    #undef ISSUE_STAGE

    // ---- epilogue: gated = out * U, split to bf16 hi/lo ----
    #pragma unroll
    for (int nt = 0; nt < 8; nt++) {
        const int d0 = nt * 8 + (l & 3) * 2;
        #pragma unroll
        for (int half = 0; half < 2; half++) {
            const int rr = qt * 128 + w * 16 + (l >> 2) + half * 8;
            const size_t grow = (size_t)(b * SEQ + rr);
            float2 u2 = *(const float2*)&g_act[grow * FOURH + h * HD + d0];
            float v0 = oacc[nt][half * 2 + 0] * u2.x;
            float v1 = oacc[nt][half * 2 + 1] * u2.y;
            __nv_bfloat16 h0 = __float2bfloat16(v0);
            __nv_bfloat16 h1 = __float2bfloat16(v1);
            size_t o = grow * HIDDEN + h * HD + d0;
            *(uint32_t*)&g_ghi[o] = pack_bf2(h0, h1);
            *(uint32_t*)&g_glo[o] =
                pack_bf2(__float2bfloat16(v0 - __bfloat162float(h0)),
                         __float2bfloat16(v1 - __bfloat162float(h1)));
        }
    }
}

// ---------------------------------------------------------------------------
// Launch. Inputs: x, W1, b1, W2, b2, rel_table, attn_mask (ignored: always
// the causal tril by construction; causality applied analytically).
// ---------------------------------------------------------------------------
extern "C" void kernel_launch(void* const* d_in, const int* in_sizes, int n_in,
                              void* d_out, int out_size)
{
    const float* x   = (const float*)d_in[0];
    const float* W1  = (const float*)d_in[1];
    const float* b1  = (const float*)d_in[2];
    const float* W2  = (const float*)d_in[3];
    const float* b2  = (const float*)d_in[4];
    const float* rel = (const float*)d_in[5];
    float* out = (float*)d_out;

    float *act_p;
    __nv_bfloat16 *acthi, *actlo, *xhi, *xlo, *w1hi, *w1lo, *w2hi, *w2lo, *ghi, *glo;
    cudaGetSymbolAddress((void**)&act_p, g_act);
    cudaGetSymbolAddress((void**)&acthi, g_acthi);
    cudaGetSymbolAddress((void**)&actlo, g_actlo);
    cudaGetSymbolAddress((void**)&xhi, g_xhi);
    cudaGetSymbolAddress((void**)&xlo, g_xlo);
    cudaGetSymbolAddress((void**)&w1hi, g_w1hi);
    cudaGetSymbolAddress((void**)&w1lo, g_w1lo);
    cudaGetSymbolAddress((void**)&w2hi, g_w2hi);
    cudaGetSymbolAddress((void**)&w2lo, g_w2lo);
    cudaGetSymbolAddress((void**)&ghi, g_ghi);
    cudaGetSymbolAddress((void**)&glo, g_glo);

    cudaFuncSetAttribute(mma_gemm, cudaFuncAttributeMaxDynamicSharedMemorySize,
                         GEMM_SMEM);
    cudaFuncSetAttribute(attn_mma, cudaFuncAttributeMaxDynamicSharedMemorySize,
                         ATTN_SMEM);

    // Conversions
    split_kernel<<<(MTOT * HIDDEN) / 256, 256>>>(x, xhi, xlo, MTOT * HIDDEN);
    transpose_split<<<dim3(FOURH / 32, HIDDEN / 32), dim3(32, 8)>>>(W1, w1hi, w1lo,
                                                                    HIDDEN, FOURH);
    transpose_split<<<dim3(HIDDEN / 32, HIDDEN / 32), dim3(32, 8)>>>(W2, w2hi, w2lo,
                                                                     HIDDEN, HIDDEN);
    // GEMM1: activated = silu(x @ W1 + b1) -> fp32 + bf16 hi/lo
    mma_gemm<<<dim3(FOURH / 128, MTOT / 128), 256, GEMM_SMEM>>>(
        xhi, xlo, w1hi, w1lo, b1, act_p, acthi, actlo, FOURH, HIDDEN, 1);
    // V^T split for attention's S@V operand
    v_transpose_split<<<dim3(SEQ / 32, HIDDEN / 32, BATCH), dim3(32, 8)>>>();
    // Tensor-core attention + gating -> g_ghi/g_glo
    attn_mma<<<dim3(SEQ / 128, HEADS, BATCH), 256, ATTN_SMEM>>>(rel);
    // GEMM2: out = gated @ W2 + b2
    mma_gemm<<<dim3(HIDDEN / 128, MTOT / 128), 256, GEMM_SMEM>>>(
        ghi, glo, w2hi, w2lo, b2, out, nullptr, nullptr, HIDDEN, HIDDEN, 0);
}

// round 10
// speedup vs baseline: 2.7707x; 1.1109x over previous
#include <cuda_runtime.h>
#include <cuda_bf16.h>
#include <cstdint>

#define HIDDEN 1024
#define FOURH  4096
#define HEADS  16
#define HD     64
#define SEQ    2048
#define BATCH  2
#define MTOT   (BATCH * SEQ)   // 4096
#define MAXSEQ 2048

// ---------------------------------------------------------------------------
// Scratch (__device__ globals; allocation-free rule)
// ---------------------------------------------------------------------------
__device__ float g_act[(size_t)MTOT * FOURH];                          // silu(x@W1+b1) fp32
__device__ __align__(16) __nv_bfloat16 g_acthi[(size_t)MTOT * FOURH];  // act split
__device__ __align__(16) __nv_bfloat16 g_actlo[(size_t)MTOT * FOURH];
__device__ __align__(16) __nv_bfloat16 g_xhi[(size_t)MTOT * HIDDEN];   // x split
__device__ __align__(16) __nv_bfloat16 g_xlo[(size_t)MTOT * HIDDEN];
__device__ __align__(16) __nv_bfloat16 g_w1hi[(size_t)FOURH * HIDDEN]; // W1^T split
__device__ __align__(16) __nv_bfloat16 g_w1lo[(size_t)FOURH * HIDDEN];
__device__ __align__(16) __nv_bfloat16 g_w2hi[(size_t)HIDDEN * HIDDEN];
__device__ __align__(16) __nv_bfloat16 g_w2lo[(size_t)HIDDEN * HIDDEN];
__device__ __align__(16) __nv_bfloat16 g_vthi[(size_t)BATCH * HIDDEN * SEQ]; // V^T [b,h,d,s]
__device__ __align__(16) __nv_bfloat16 g_vtlo[(size_t)BATCH * HIDDEN * SEQ];
__device__ __align__(16) __nv_bfloat16 g_ghi[(size_t)MTOT * HIDDEN];   // gated split
__device__ __align__(16) __nv_bfloat16 g_glo[(size_t)MTOT * HIDDEN];

__device__ __forceinline__ float silu_f(float x) {
    return __fdividef(x, 1.0f + __expf(-x));
}

__device__ __forceinline__ uint32_t s2u(const void* p) {
    uint32_t a;
    asm("{ .reg .u64 t; cvta.to.shared.u64 t, %1; cvt.u32.u64 %0, t; }"
        : "=r"(a) : "l"(p));
    return a;
}

#define CP_ASYNC16(sa, ga) \
    asm volatile("cp.async.cg.shared.global [%0], [%1], 16;" \
                 :: "r"(sa), "l"(ga) : "memory")
#define CP_COMMIT()  asm volatile("cp.async.commit_group;" ::: "memory")
#define CP_WAIT1()   asm volatile("cp.async.wait_group 1;" ::: "memory")
#define CP_WAIT0()   asm volatile("cp.async.wait_group 0;" ::: "memory")

#define LDSM4(r, addr) \
    asm volatile("ldmatrix.sync.aligned.m8n8.x4.shared.b16 {%0,%1,%2,%3}, [%4];" \
                 : "=r"((r)[0]), "=r"((r)[1]), "=r"((r)[2]), "=r"((r)[3]) \
                 : "r"(addr))

#define MMA16816(c, a, b0, b1) \
    asm volatile("mma.sync.aligned.m16n8k16.row.col.f32.bf16.bf16.f32 " \
                 "{%0,%1,%2,%3}, {%4,%5,%6,%7}, {%8,%9}, {%0,%1,%2,%3};" \
                 : "+f"((c)[0]), "+f"((c)[1]), "+f"((c)[2]), "+f"((c)[3]) \
                 : "r"((a)[0]), "r"((a)[1]), "r"((a)[2]), "r"((a)[3]), \
                   "r"(b0), "r"(b1))

__device__ __forceinline__ uint32_t pack_bf2(__nv_bfloat16 lo, __nv_bfloat16 hi) {
    __nv_bfloat162 t(lo, hi);
    return *(uint32_t*)&t;
}

// ---------------------------------------------------------------------------
// Conversion kernels
// ---------------------------------------------------------------------------
__global__ void split_kernel(const float* __restrict__ src,
                             __nv_bfloat16* __restrict__ hi,
                             __nv_bfloat16* __restrict__ lo, int n)
{
    int i = blockIdx.x * blockDim.x + threadIdx.x;
    if (i < n) {
        float v = src[i];
        __nv_bfloat16 h = __float2bfloat16(v);
        hi[i] = h;
        lo[i] = __float2bfloat16(v - __bfloat162float(h));
    }
}

// W [K, N] row-major -> W^T hi/lo [N, K]
__global__ void transpose_split(const float* __restrict__ W,
                                __nv_bfloat16* __restrict__ Thi,
                                __nv_bfloat16* __restrict__ Tlo, int K, int N)
{
    __shared__ float t[32][33];
    int tx = threadIdx.x, ty = threadIdx.y;
    int n0 = blockIdx.x * 32, k0 = blockIdx.y * 32;
    #pragma unroll
    for (int i = 0; i < 4; i++)
        t[ty + 8 * i][tx] = W[(size_t)(k0 + ty + 8 * i) * N + n0 + tx];
    __syncthreads();
    #pragma unroll
    for (int i = 0; i < 4; i++) {
        int n = ty + 8 * i;
        float v = t[tx][n];
        __nv_bfloat16 h = __float2bfloat16(v);
        size_t o = (size_t)(n0 + n) * K + k0 + tx;
        Thi[o] = h;
        Tlo[o] = __float2bfloat16(v - __bfloat162float(h));
    }
}

// V region of g_act (cols 3072..4095) -> V^T hi/lo [b, h, d, s]
__global__ void v_transpose_split()
{
    __shared__ float t[32][33];
    int tx = threadIdx.x, ty = threadIdx.y;
    int s0 = blockIdx.x * 32, c0 = blockIdx.y * 32, b = blockIdx.z;
    #pragma unroll
    for (int i = 0; i < 4; i++)
        t[ty + 8 * i][tx] =
            g_act[(size_t)(b * SEQ + s0 + ty + 8 * i) * FOURH + 3 * HIDDEN + c0 + tx];
    __syncthreads();
    #pragma unroll
    for (int i = 0; i < 4; i++) {
        int cl = ty + 8 * i;
        int c = c0 + cl;
        int hh = c >> 6, d = c & 63;
        float v = t[tx][cl];
        __nv_bfloat16 h = __float2bfloat16(v);
        size_t o = (size_t)((b * HEADS + hh) * HD + d) * SEQ + s0 + tx;
        g_vthi[o] = h;
        g_vtlo[o] = __float2bfloat16(v - __bfloat162float(h));
    }
}

// ---------------------------------------------------------------------------
// mma.sync bf16 GEMM, 3-product fp32 emulation.
// CTA tile 128x128, BK=32, 4 warps (2m x 2n), warp tile 64x64.
// 128 threads/CTA, 2 CTAs/SM. MMA:LDSM ratio 6.0.
// offB FIX vs round 8: B lane map is (l>>4)->n-row-group, ((l>>3)&1)->k-chunk
// (round-6 validated map), NOT the A-style map.
// ---------------------------------------------------------------------------
#define STAGE_BYTES (4 * 128 * 80)          // 40960
#define GEMM_SMEM   (2 * STAGE_BYTES)       // 81920

__global__ __launch_bounds__(128, 2) void mma_gemm(
    const __nv_bfloat16* __restrict__ Ahi, const __nv_bfloat16* __restrict__ Alo,
    const __nv_bfloat16* __restrict__ BThi, const __nv_bfloat16* __restrict__ BTlo,
    const float* __restrict__ bias, float* __restrict__ C,
    __nv_bfloat16* __restrict__ Chi, __nv_bfloat16* __restrict__ Clo,
    int N, int K, int do_silu)
{
    extern __shared__ __align__(128) char sm_raw[];
    const uint32_t sbase = s2u(sm_raw);

    const int tid = threadIdx.x;
    const int m0 = blockIdx.y << 7;
    const int n0 = blockIdx.x << 7;

    const __nv_bfloat16* gsrc[4] = {
        Ahi + (size_t)m0 * K, Alo + (size_t)m0 * K,
        BThi + (size_t)n0 * K, BTlo + (size_t)n0 * K };

    // loader: per array 128 rows x 4 16B-chunks = 512 chunks; 4 per thread
    const int lr = tid >> 2;         // 0..31 (rows lr, lr+32, lr+64, lr+96)
    const int lc = tid & 3;

    const int wid = tid >> 5, l = tid & 31;
    const int wm = wid >> 1;         // 0..1
    const int wn = wid & 1;          // 0..1
    const uint32_t offA = (uint32_t)((wm * 64 + ((l >> 3) & 1) * 8 + (l & 7)) * 80
                                     + (l >> 4) * 16);
    const uint32_t offB = (uint32_t)((wn * 64 + (l >> 4) * 8 + (l & 7)) * 80
                                     + ((l >> 3) & 1) * 16);

    float acc[4][8][4] = {};
    const int NS = K >> 5;

    // prologue: stage 0
    {
        #pragma unroll
        for (int t = 0; t < 4; t++) {
            const __nv_bfloat16* g = gsrc[t] + lc * 8;
            const uint32_t sa = sbase + t * 10240 + lr * 80 + lc * 16;
            #pragma unroll
            for (int i = 0; i < 4; i++)
                CP_ASYNC16(sa + i * (32 * 80), g + (size_t)(lr + 32 * i) * K);
        }
        CP_COMMIT();
    }

    for (int s = 0; s < NS; s++) {
        if (s + 1 < NS) {
            const int k0 = (s + 1) << 5;
            const uint32_t sb = sbase + ((s + 1) & 1) * STAGE_BYTES;
            #pragma unroll
            for (int t = 0; t < 4; t++) {
                const __nv_bfloat16* g = gsrc[t] + k0 + lc * 8;
                const uint32_t sa = sb + t * 10240 + lr * 80 + lc * 16;
                #pragma unroll
                for (int i = 0; i < 4; i++)
                    CP_ASYNC16(sa + i * (32 * 80), g + (size_t)(lr + 32 * i) * K);
            }
            CP_COMMIT();
            CP_WAIT1();
        } else {
            CP_WAIT0();
        }
        __syncthreads();

        const uint32_t sb = sbase + (s & 1) * STAGE_BYTES;
        const uint32_t aH = sb, aL = sb + 10240, bH = sb + 20480, bL = sb + 30720;

        #pragma unroll
        for (int ks = 0; ks < 2; ks++) {
            uint32_t fa_h[4][4], fa_l[4][4];
            #pragma unroll
            for (int mt = 0; mt < 4; mt++) {
                LDSM4(fa_h[mt], aH + offA + mt * (16 * 80) + ks * 32);
                LDSM4(fa_l[mt], aL + offA + mt * (16 * 80) + ks * 32);
            }
            #pragma unroll
            for (int np = 0; np < 4; np++) {
                uint32_t rh[4], rl[4];
                LDSM4(rh, bH + offB + np * (16 * 80) + ks * 32);
                LDSM4(rl, bL + offB + np * (16 * 80) + ks * 32);
                #pragma unroll
                for (int t = 0; t < 2; t++) {
                    const int nt = np * 2 + t;
                    #pragma unroll
                    for (int mt = 0; mt < 4; mt++) {
                        MMA16816(acc[mt][nt], fa_h[mt], rh[t * 2], rh[t * 2 + 1]);
                        MMA16816(acc[mt][nt], fa_h[mt], rl[t * 2], rl[t * 2 + 1]);
                        MMA16816(acc[mt][nt], fa_l[mt], rh[t * 2], rh[t * 2 + 1]);
                    }
                }
            }
        }
        __syncthreads();
    }

    // epilogue: bias + optional silu (+ optional bf16 hi/lo split of C)
    const int rbase = m0 + wm * 64 + (l >> 2);
    const int cbase = n0 + wn * 64 + (l & 3) * 2;
    #pragma unroll
    for (int nt = 0; nt < 8; nt++) {
        const int col = cbase + nt * 8;
        const float bx = bias[col], by = bias[col + 1];
        #pragma unroll
        for (int mt = 0; mt < 4; mt++) {
            #pragma unroll
            for (int half = 0; half < 2; half++) {
                const int row = rbase + mt * 16 + half * 8;
                float v0 = acc[mt][nt][half * 2 + 0] + bx;
                float v1 = acc[mt][nt][half * 2 + 1] + by;
                if (do_silu) { v0 = silu_f(v0); v1 = silu_f(v1); }
                *(float2*)&C[(size_t)row * N + col] = make_float2(v0, v1);
                if (Chi) {
                    __nv_bfloat16 h0 = __float2bfloat16(v0);
                    __nv_bfloat16 h1 = __float2bfloat16(v1);
                    __nv_bfloat16 l0 = __float2bfloat16(v0 - __bfloat162float(h0));
                    __nv_bfloat16 l1 = __float2bfloat16(v1 - __bfloat162float(h1));
                    *(uint32_t*)&Chi[(size_t)row * N + col] = pack_bf2(h0, h1);
                    *(uint32_t*)&Clo[(size_t)row * N + col] = pack_bf2(l0, l1);
                }
            }
        }
    }
}

// ---------------------------------------------------------------------------
// Tensor-core HSTU attention (round-7, validated).
// ---------------------------------------------------------------------------
#define AP     72
#define ST_KH  0
#define ST_KL  9216
#define ST_VH  18432
#define ST_VL  27648
#define ST_SZ  36864
#define ATTN_SMEM (2 * ST_SZ)           // 73728

__global__ __launch_bounds__(256) void attn_mma(const float* __restrict__ rel_table)
{
    const int qt = gridDim.x - 1 - blockIdx.x;  // long tiles first
    const int h  = blockIdx.y;
    const int b  = blockIdx.z;

    extern __shared__ __align__(128) char smraw[];
    const uint32_t sb0 = s2u(smraw);
    __shared__ float bias_s[192];

    const int tid = threadIdx.x;
    const int w = tid >> 5, l = tid & 31;

    // ---- Q tile (128 x 64 hi+lo) via cp.async into stage0 area ----
    {
        const int arr = tid >> 7;
        const int u = tid & 127;
        const __nv_bfloat16* src = arr ? g_actlo : g_acthi;
        const uint32_t qb = sb0 + arr * 18432;
        #pragma unroll
        for (int i = 0; i < 8; i++) {
            int r = (u >> 3) + 16 * i;
            int c = u & 7;
            CP_ASYNC16(qb + r * 144 + c * 16,
                       src + (size_t)(b * SEQ + qt * 128 + r) * FOURH
                           + HIDDEN + h * HD + c * 8);
        }
        CP_COMMIT();
        CP_WAIT0();
    }
    __syncthreads();

    uint32_t qh[4][4], ql[4][4];
    #pragma unroll
    for (int kc = 0; kc < 4; kc++) {
        uint32_t a = sb0 + (uint32_t)((w * 16 + ((l >> 3) & 1) * 8 + (l & 7)) * AP
                                      + kc * 16 + (l >> 4) * 8) * 2;
        LDSM4(qh[kc], a);
        LDSM4(ql[kc], a + 18432);
    }
    __syncthreads();

    float oacc[8][4] = {};
    const int ktmax = 2 * qt + 1;

    const int arr = tid >> 6;
    const int u = tid & 63;
    const size_t krow0 = (size_t)(b * SEQ) * FOURH + 2 * HIDDEN + h * HD;
    const size_t vrow0 = (size_t)((b * HEADS + h) * HD) * SEQ;

    #define ISSUE_STAGE(buf, ktv) do {                                         \
        const uint32_t base_ = sb0 + (buf) * ST_SZ + arr * 9216;               \
        _Pragma("unroll")                                                      \
        for (int i_ = 0; i_ < 8; i_++) {                                       \
            int r_ = (u >> 3) + 8 * i_;                                        \
            int c_ = u & 7;                                                    \
            const __nv_bfloat16* g_;                                           \
            if (arr == 0)                                                      \
                g_ = g_acthi + krow0 + (size_t)((ktv) * 64 + r_) * FOURH + c_ * 8; \
            else if (arr == 1)                                                 \
                g_ = g_actlo + krow0 + (size_t)((ktv) * 64 + r_) * FOURH + c_ * 8; \
            else if (arr == 2)                                                 \
                g_ = g_vthi + vrow0 + (size_t)r_ * SEQ + (ktv) * 64 + c_ * 8;  \
            else                                                               \
                g_ = g_vtlo + vrow0 + (size_t)r_ * SEQ + (ktv) * 64 + c_ * 8;  \
            CP_ASYNC16(base_ + r_ * 144 + c_ * 16, g_);                        \
        }                                                                      \
    } while (0)

    ISSUE_STAGE(0, 0);
    CP_COMMIT();

    for (int kt = 0; kt <= ktmax; kt++) {
        if (kt < ktmax) {
            ISSUE_STAGE((kt + 1) & 1, kt + 1);
            CP_COMMIT();
            CP_WAIT1();
        } else {
            CP_WAIT0();
        }
        if (tid < 191)
            bias_s[tid] = rel_table[(size_t)(qt * 128 - kt * 64 - 63 + tid
                                             + MAXSEQ - 1) * HEADS + h];
        __syncthreads();

        const uint32_t stg = sb0 + (kt & 1) * ST_SZ;
        const uint32_t offB = (uint32_t)(((l >> 4) * 8 + (l & 7)) * AP
                                         + ((l >> 3) & 1) * 8) * 2;

        // ---- S = Q K^T (3-product) ----
        float sacc[8][4] = {};
        #pragma unroll
        for (int kc = 0; kc < 4; kc++) {
            #pragma unroll
            for (int ntp = 0; ntp < 4; ntp++) {
                uint32_t addr = stg + offB + (uint32_t)(ntp * 16 * AP + kc * 16) * 2;
                uint32_t kh[4], kl[4];
                LDSM4(kh, addr + ST_KH);
                LDSM4(kl, addr + ST_KL);
                #pragma unroll
                for (int t = 0; t < 2; t++) {
                    int nt = ntp * 2 + t;
                    MMA16816(sacc[nt], qh[kc], kh[t * 2], kh[t * 2 + 1]);
                    MMA16816(sacc[nt], qh[kc], kl[t * 2], kl[t * 2 + 1]);
                    MMA16816(sacc[nt], ql[kc], kh[t * 2], kh[t * 2 + 1]);
                }
            }
        }

        // ---- scale + bias + silu + causal mask; split to bf16 hi/lo ----
        uint32_t shi[8][2], slo[8][2];
        #pragma unroll
        for (int nt = 0; nt < 8; nt++) {
            const int c0 = nt * 8 + (l & 3) * 2;
            const int r0 = w * 16 + (l >> 2);
            float vv[4];
            #pragma unroll
            for (int e = 0; e < 4; e++) {
                int rr = r0 + (e >> 1) * 8;
                int cc = c0 + (e & 1);
                float v = sacc[nt][e] * 0.125f + bias_s[rr - cc + 63];
                v = silu_f(v);
                vv[e] = ((kt * 64 + cc) <= (qt * 128 + rr)) ? v : 0.0f;
            }
            __nv_bfloat16 h0 = __float2bfloat16(vv[0]);
            __nv_bfloat16 h1 = __float2bfloat16(vv[1]);
            __nv_bfloat16 h2 = __float2bfloat16(vv[2]);
            __nv_bfloat16 h3 = __float2bfloat16(vv[3]);
            shi[nt][0] = pack_bf2(h0, h1);
            shi[nt][1] = pack_bf2(h2, h3);
            slo[nt][0] = pack_bf2(__float2bfloat16(vv[0] - __bfloat162float(h0)),
                                  __float2bfloat16(vv[1] - __bfloat162float(h1)));
            slo[nt][1] = pack_bf2(__float2bfloat16(vv[2] - __bfloat162float(h2)),
                                  __float2bfloat16(vv[3] - __bfloat162float(h3)));
        }

        // ---- out += S @ V (3-product; S accum frags reused as A frags) ----
        #pragma unroll
        for (int kc2 = 0; kc2 < 4; kc2++) {
            uint32_t ah[4] = { shi[2 * kc2][0], shi[2 * kc2][1],
                               shi[2 * kc2 + 1][0], shi[2 * kc2 + 1][1] };
            uint32_t al[4] = { slo[2 * kc2][0], slo[2 * kc2][1],
                               slo[2 * kc2 + 1][0], slo[2 * kc2 + 1][1] };
            #pragma unroll
            for (int ntp = 0; ntp < 4; ntp++) {
                uint32_t addr = stg + offB + (uint32_t)(ntp * 16 * AP + kc2 * 16) * 2;
                uint32_t vh[4], vl[4];
                LDSM4(vh, addr + ST_VH);
                LDSM4(vl, addr + ST_VL);
                #pragma unroll
                for (int t = 0; t < 2; t++) {
                    int nt = ntp * 2 + t;
                    MMA16816(oacc[nt], ah, vh[t * 2], vh[t * 2 + 1]);
                    MMA16816(oacc[nt], ah, vl[t * 2], vl[t * 2 + 1]);
                    MMA16816(oacc[nt], al, vh[t * 2], vh[t * 2 + 1]);
                }
            }
        }
        __syncthreads();
    }
    #undef ISSUE_STAGE

    // ---- epilogue: gated = out * U, split to bf16 hi/lo ----
    #pragma unroll
    for (int nt = 0; nt < 8; nt++) {
        const int d0 = nt * 8 + (l & 3) * 2;
        #pragma unroll
        for (int half = 0; half < 2; half++) {
            const int rr = qt * 128 + w * 16 + (l >> 2) + half * 8;
            const size_t grow = (size_t)(b * SEQ + rr);
            float2 u2 = *(const float2*)&g_act[grow * FOURH + h * HD + d0];
            float v0 = oacc[nt][half * 2 + 0] * u2.x;
            float v1 = oacc[nt][half * 2 + 1] * u2.y;
            __nv_bfloat16 h0 = __float2bfloat16(v0);
            __nv_bfloat16 h1 = __float2bfloat16(v1);
            size_t o = grow * HIDDEN + h * HD + d0;
            *(uint32_t*)&g_ghi[o] = pack_bf2(h0, h1);
            *(uint32_t*)&g_glo[o] =
                pack_bf2(__float2bfloat16(v0 - __bfloat162float(h0)),
                         __float2bfloat16(v1 - __bfloat162float(h1)));
        }
    }
}

// ---------------------------------------------------------------------------
// Launch. Inputs: x, W1, b1, W2, b2, rel_table, attn_mask (ignored: always
// the causal tril by construction; causality applied analytically).
// ---------------------------------------------------------------------------
extern "C" void kernel_launch(void* const* d_in, const int* in_sizes, int n_in,
                              void* d_out, int out_size)
{
    const float* x   = (const float*)d_in[0];
    const float* W1  = (const float*)d_in[1];
    const float* b1  = (const float*)d_in[2];
    const float* W2  = (const float*)d_in[3];
    const float* b2  = (const float*)d_in[4];
    const float* rel = (const float*)d_in[5];
    float* out = (float*)d_out;

    float *act_p;
    __nv_bfloat16 *acthi, *actlo, *xhi, *xlo, *w1hi, *w1lo, *w2hi, *w2lo, *ghi, *glo;
    cudaGetSymbolAddress((void**)&act_p, g_act);
    cudaGetSymbolAddress((void**)&acthi, g_acthi);
    cudaGetSymbolAddress((void**)&actlo, g_actlo);
    cudaGetSymbolAddress((void**)&xhi, g_xhi);
    cudaGetSymbolAddress((void**)&xlo, g_xlo);
    cudaGetSymbolAddress((void**)&w1hi, g_w1hi);
    cudaGetSymbolAddress((void**)&w1lo, g_w1lo);
    cudaGetSymbolAddress((void**)&w2hi, g_w2hi);
    cudaGetSymbolAddress((void**)&w2lo, g_w2lo);
    cudaGetSymbolAddress((void**)&ghi, g_ghi);
    cudaGetSymbolAddress((void**)&glo, g_glo);

    cudaFuncSetAttribute(mma_gemm, cudaFuncAttributeMaxDynamicSharedMemorySize,
                         GEMM_SMEM);
    cudaFuncSetAttribute(attn_mma, cudaFuncAttributeMaxDynamicSharedMemorySize,
                         ATTN_SMEM);

    // Conversions
    split_kernel<<<(MTOT * HIDDEN) / 256, 256>>>(x, xhi, xlo, MTOT * HIDDEN);
    transpose_split<<<dim3(FOURH / 32, HIDDEN / 32), dim3(32, 8)>>>(W1, w1hi, w1lo,
                                                                    HIDDEN, FOURH);
    transpose_split<<<dim3(HIDDEN / 32, HIDDEN / 32), dim3(32, 8)>>>(W2, w2hi, w2lo,
                                                                     HIDDEN, HIDDEN);
    // GEMM1: activated = silu(x @ W1 + b1) -> fp32 + bf16 hi/lo
    mma_gemm<<<dim3(FOURH / 128, MTOT / 128), 128, GEMM_SMEM>>>(
        xhi, xlo, w1hi, w1lo, b1, act_p, acthi, actlo, FOURH, HIDDEN, 1);
    // V^T split for attention's S@V operand
    v_transpose_split<<<dim3(SEQ / 32, HIDDEN / 32, BATCH), dim3(32, 8)>>>();
    // Tensor-core attention + gating -> g_ghi/g_glo
    attn_mma<<<dim3(SEQ / 128, HEADS, BATCH), 256, ATTN_SMEM>>>(rel);
    // GEMM2: out = gated @ W2 + b2
    mma_gemm<<<dim3(HIDDEN / 128, MTOT / 128), 128, GEMM_SMEM>>>(
        ghi, glo, w2hi, w2lo, b2, out, nullptr, nullptr, HIDDEN, HIDDEN, 0);
}

// round 11
// speedup vs baseline: 3.1051x; 1.1207x over previous
#include <cuda_runtime.h>
#include <cuda_bf16.h>
#include <cstdint>

#define HIDDEN 1024
#define FOURH  4096
#define HEADS  16
#define HD     64
#define SEQ    2048
#define BATCH  2
#define MTOT   (BATCH * SEQ)   // 4096
#define MAXSEQ 2048

// ---------------------------------------------------------------------------
// Scratch (__device__ globals; allocation-free rule)
// ---------------------------------------------------------------------------
__device__ __align__(16) __nv_bfloat16 g_acthi[(size_t)MTOT * FOURH];  // act split
__device__ __align__(16) __nv_bfloat16 g_actlo[(size_t)MTOT * FOURH];
__device__ __align__(16) __nv_bfloat16 g_xhi[(size_t)MTOT * HIDDEN];   // x split
__device__ __align__(16) __nv_bfloat16 g_xlo[(size_t)MTOT * HIDDEN];
__device__ __align__(16) __nv_bfloat16 g_w1hi[(size_t)FOURH * HIDDEN]; // W1^T split
__device__ __align__(16) __nv_bfloat16 g_w1lo[(size_t)FOURH * HIDDEN];
__device__ __align__(16) __nv_bfloat16 g_w2hi[(size_t)HIDDEN * HIDDEN];
__device__ __align__(16) __nv_bfloat16 g_w2lo[(size_t)HIDDEN * HIDDEN];
__device__ __align__(16) __nv_bfloat16 g_vthi[(size_t)BATCH * HIDDEN * SEQ]; // V^T [b,h,d,s]
__device__ __align__(16) __nv_bfloat16 g_vtlo[(size_t)BATCH * HIDDEN * SEQ];
__device__ __align__(16) __nv_bfloat16 g_ghi[(size_t)MTOT * HIDDEN];   // gated split
__device__ __align__(16) __nv_bfloat16 g_glo[(size_t)MTOT * HIDDEN];

__device__ __forceinline__ float silu_f(float x) {
    return __fdividef(x, 1.0f + __expf(-x));
}

__device__ __forceinline__ uint32_t s2u(const void* p) {
    uint32_t a;
    asm("{ .reg .u64 t; cvta.to.shared.u64 t, %1; cvt.u32.u64 %0, t; }"
        : "=r"(a) : "l"(p));
    return a;
}

#define CP_ASYNC16(sa, ga) \
    asm volatile("cp.async.cg.shared.global [%0], [%1], 16;" \
                 :: "r"(sa), "l"(ga) : "memory")
#define CP_COMMIT()  asm volatile("cp.async.commit_group;" ::: "memory")
#define CP_WAIT1()   asm volatile("cp.async.wait_group 1;" ::: "memory")
#define CP_WAIT0()   asm volatile("cp.async.wait_group 0;" ::: "memory")

#define LDSM4(r, addr) \
    asm volatile("ldmatrix.sync.aligned.m8n8.x4.shared.b16 {%0,%1,%2,%3}, [%4];" \
                 : "=r"((r)[0]), "=r"((r)[1]), "=r"((r)[2]), "=r"((r)[3]) \
                 : "r"(addr))

#define MMA16816(c, a, b0, b1) \
    asm volatile("mma.sync.aligned.m16n8k16.row.col.f32.bf16.bf16.f32 " \
                 "{%0,%1,%2,%3}, {%4,%5,%6,%7}, {%8,%9}, {%0,%1,%2,%3};" \
                 : "+f"((c)[0]), "+f"((c)[1]), "+f"((c)[2]), "+f"((c)[3]) \
                 : "r"((a)[0]), "r"((a)[1]), "r"((a)[2]), "r"((a)[3]), \
                   "r"(b0), "r"(b1))

__device__ __forceinline__ uint32_t pack_bf2(__nv_bfloat16 lo, __nv_bfloat16 hi) {
    __nv_bfloat162 t(lo, hi);
    return *(uint32_t*)&t;
}

// ---------------------------------------------------------------------------
// Conversion kernels
// ---------------------------------------------------------------------------
__global__ void split_kernel(const float* __restrict__ src,
                             __nv_bfloat16* __restrict__ hi,
                             __nv_bfloat16* __restrict__ lo, int n)
{
    int i = blockIdx.x * blockDim.x + threadIdx.x;
    if (i < n) {
        float v = src[i];
        __nv_bfloat16 h = __float2bfloat16(v);
        hi[i] = h;
        lo[i] = __float2bfloat16(v - __bfloat162float(h));
    }
}

// W [K, N] row-major -> W^T hi/lo [N, K]
__global__ void transpose_split(const float* __restrict__ W,
                                __nv_bfloat16* __restrict__ Thi,
                                __nv_bfloat16* __restrict__ Tlo, int K, int N)
{
    __shared__ float t[32][33];
    int tx = threadIdx.x, ty = threadIdx.y;
    int n0 = blockIdx.x * 32, k0 = blockIdx.y * 32;
    #pragma unroll
    for (int i = 0; i < 4; i++)
        t[ty + 8 * i][tx] = W[(size_t)(k0 + ty + 8 * i) * N + n0 + tx];
    __syncthreads();
    #pragma unroll
    for (int i = 0; i < 4; i++) {
        int n = ty + 8 * i;
        float v = t[tx][n];
        __nv_bfloat16 h = __float2bfloat16(v);
        size_t o = (size_t)(n0 + n) * K + k0 + tx;
        Thi[o] = h;
        Tlo[o] = __float2bfloat16(v - __bfloat162float(h));
    }
}

// V region of acthi/actlo (cols 3072..4095) -> V^T hi/lo [b, h, d, s].
// Pure bf16 transpose: vthi = transpose(acthi_V), vtlo = transpose(actlo_V).
__global__ void v_transpose_bf16()
{
    __shared__ float th[32][33], tl[32][33];
    int tx = threadIdx.x, ty = threadIdx.y;
    int s0 = blockIdx.x * 32, c0 = blockIdx.y * 32, b = blockIdx.z;
    #pragma unroll
    for (int i = 0; i < 4; i++) {
        size_t o = (size_t)(b * SEQ + s0 + ty + 8 * i) * FOURH + 3 * HIDDEN + c0 + tx;
        th[ty + 8 * i][tx] = __bfloat162float(g_acthi[o]);
        tl[ty + 8 * i][tx] = __bfloat162float(g_actlo[o]);
    }
    __syncthreads();
    #pragma unroll
    for (int i = 0; i < 4; i++) {
        int cl = ty + 8 * i;
        int c = c0 + cl;
        int hh = c >> 6, d = c & 63;
        size_t o = (size_t)((b * HEADS + hh) * HD + d) * SEQ + s0 + tx;
        g_vthi[o] = __float2bfloat16(th[tx][cl]);   // exact roundtrip
        g_vtlo[o] = __float2bfloat16(tl[tx][cl]);
    }
}

// ---------------------------------------------------------------------------
// mma.sync bf16 GEMM, 3-product fp32 emulation (round-10, validated).
// CTA 128x128, BK=32, 4 warps (2m x 2n), 64x64 warp tile, 2 CTAs/SM.
// C (fp32) and Chi/Clo (bf16 split) outputs each optional.
// ---------------------------------------------------------------------------
#define STAGE_BYTES (4 * 128 * 80)          // 40960
#define GEMM_SMEM   (2 * STAGE_BYTES)       // 81920

__global__ __launch_bounds__(128, 2) void mma_gemm(
    const __nv_bfloat16* __restrict__ Ahi, const __nv_bfloat16* __restrict__ Alo,
    const __nv_bfloat16* __restrict__ BThi, const __nv_bfloat16* __restrict__ BTlo,
    const float* __restrict__ bias, float* __restrict__ C,
    __nv_bfloat16* __restrict__ Chi, __nv_bfloat16* __restrict__ Clo,
    int N, int K, int do_silu)
{
    extern __shared__ __align__(128) char sm_raw[];
    const uint32_t sbase = s2u(sm_raw);

    const int tid = threadIdx.x;
    const int m0 = blockIdx.y << 7;
    const int n0 = blockIdx.x << 7;

    const __nv_bfloat16* gsrc[4] = {
        Ahi + (size_t)m0 * K, Alo + (size_t)m0 * K,
        BThi + (size_t)n0 * K, BTlo + (size_t)n0 * K };

    const int lr = tid >> 2;         // 0..31 (rows lr, lr+32, lr+64, lr+96)
    const int lc = tid & 3;

    const int wid = tid >> 5, l = tid & 31;
    const int wm = wid >> 1;
    const int wn = wid & 1;
    const uint32_t offA = (uint32_t)((wm * 64 + ((l >> 3) & 1) * 8 + (l & 7)) * 80
                                     + (l >> 4) * 16);
    const uint32_t offB = (uint32_t)((wn * 64 + (l >> 4) * 8 + (l & 7)) * 80
                                     + ((l >> 3) & 1) * 16);

    float acc[4][8][4] = {};
    const int NS = K >> 5;

    {
        #pragma unroll
        for (int t = 0; t < 4; t++) {
            const __nv_bfloat16* g = gsrc[t] + lc * 8;
            const uint32_t sa = sbase + t * 10240 + lr * 80 + lc * 16;
            #pragma unroll
            for (int i = 0; i < 4; i++)
                CP_ASYNC16(sa + i * (32 * 80), g + (size_t)(lr + 32 * i) * K);
        }
        CP_COMMIT();
    }

    for (int s = 0; s < NS; s++) {
        if (s + 1 < NS) {
            const int k0 = (s + 1) << 5;
            const uint32_t sb = sbase + ((s + 1) & 1) * STAGE_BYTES;
            #pragma unroll
            for (int t = 0; t < 4; t++) {
                const __nv_bfloat16* g = gsrc[t] + k0 + lc * 8;
                const uint32_t sa = sb + t * 10240 + lr * 80 + lc * 16;
                #pragma unroll
                for (int i = 0; i < 4; i++)
                    CP_ASYNC16(sa + i * (32 * 80), g + (size_t)(lr + 32 * i) * K);
            }
            CP_COMMIT();
            CP_WAIT1();
        } else {
            CP_WAIT0();
        }
        __syncthreads();

        const uint32_t sb = sbase + (s & 1) * STAGE_BYTES;
        const uint32_t aH = sb, aL = sb + 10240, bH = sb + 20480, bL = sb + 30720;

        #pragma unroll
        for (int ks = 0; ks < 2; ks++) {
            uint32_t fa_h[4][4], fa_l[4][4];
            #pragma unroll
            for (int mt = 0; mt < 4; mt++) {
                LDSM4(fa_h[mt], aH + offA + mt * (16 * 80) + ks * 32);
                LDSM4(fa_l[mt], aL + offA + mt * (16 * 80) + ks * 32);
            }
            #pragma unroll
            for (int np = 0; np < 4; np++) {
                uint32_t rh[4], rl[4];
                LDSM4(rh, bH + offB + np * (16 * 80) + ks * 32);
                LDSM4(rl, bL + offB + np * (16 * 80) + ks * 32);
                #pragma unroll
                for (int t = 0; t < 2; t++) {
                    const int nt = np * 2 + t;
                    #pragma unroll
                    for (int mt = 0; mt < 4; mt++) {
                        MMA16816(acc[mt][nt], fa_h[mt], rh[t * 2], rh[t * 2 + 1]);
                        MMA16816(acc[mt][nt], fa_h[mt], rl[t * 2], rl[t * 2 + 1]);
                        MMA16816(acc[mt][nt], fa_l[mt], rh[t * 2], rh[t * 2 + 1]);
                    }
                }
            }
        }
        __syncthreads();
    }

    // epilogue
    const int rbase = m0 + wm * 64 + (l >> 2);
    const int cbase = n0 + wn * 64 + (l & 3) * 2;
    #pragma unroll
    for (int nt = 0; nt < 8; nt++) {
        const int col = cbase + nt * 8;
        const float bx = bias[col], by = bias[col + 1];
        #pragma unroll
        for (int mt = 0; mt < 4; mt++) {
            #pragma unroll
            for (int half = 0; half < 2; half++) {
                const int row = rbase + mt * 16 + half * 8;
                float v0 = acc[mt][nt][half * 2 + 0] + bx;
                float v1 = acc[mt][nt][half * 2 + 1] + by;
                if (do_silu) { v0 = silu_f(v0); v1 = silu_f(v1); }
                if (C)
                    *(float2*)&C[(size_t)row * N + col] = make_float2(v0, v1);
                if (Chi) {
                    __nv_bfloat16 h0 = __float2bfloat16(v0);
                    __nv_bfloat16 h1 = __float2bfloat16(v1);
                    __nv_bfloat16 l0 = __float2bfloat16(v0 - __bfloat162float(h0));
                    __nv_bfloat16 l1 = __float2bfloat16(v1 - __bfloat162float(h1));
                    *(uint32_t*)&Chi[(size_t)row * N + col] = pack_bf2(h0, h1);
                    *(uint32_t*)&Clo[(size_t)row * N + col] = pack_bf2(l0, l1);
                }
            }
        }
    }
}

// ---------------------------------------------------------------------------
// Tensor-core HSTU attention, round-11:
//  - 3-stage cp.async K/V pipeline, prefetch depth 2, ONE __syncthreads/iter
//  - full rel-bias row preloaded into smem once (range [-127, 128*qt+127])
//  - U gate reconstructed from acthi+actlo (no fp32 act tensor)
// Dynamic smem: 3 stages x 36864 + 2304*4 bias = 119808 B.
// ---------------------------------------------------------------------------
#define AP     72
#define ST_KH  0
#define ST_KL  9216
#define ST_VH  18432
#define ST_VL  27648
#define ST_SZ  36864
#define BIAS_MAX 2304
#define ATTN_SMEM (3 * ST_SZ + BIAS_MAX * 4)   // 119808

__global__ __launch_bounds__(256) void attn_mma(const float* __restrict__ rel_table)
{
    const int qt = gridDim.x - 1 - blockIdx.x;  // long tiles first
    const int h  = blockIdx.y;
    const int b  = blockIdx.z;

    extern __shared__ __align__(128) char smraw[];
    const uint32_t sb0 = s2u(smraw);
    float* bias_full = (float*)(smraw + 3 * ST_SZ);

    const int tid = threadIdx.x;
    const int w = tid >> 5, l = tid & 31;

    // ---- Q tile (128 x 64 hi+lo) via cp.async into stage area ----
    {
        const int qarr = tid >> 7;
        const int u = tid & 127;
        const __nv_bfloat16* src = qarr ? g_actlo : g_acthi;
        const uint32_t qb = sb0 + qarr * 18432;
        #pragma unroll
        for (int i = 0; i < 8; i++) {
            int r = (u >> 3) + 16 * i;
            int c = u & 7;
            CP_ASYNC16(qb + r * 144 + c * 16,
                       src + (size_t)(b * SEQ + qt * 128 + r) * FOURH
                           + HIDDEN + h * HD + c * 8);
        }
        CP_COMMIT();
    }

    // ---- bias preload (overlaps Q cp.async): delta in [-127, 128*qt+127] ----
    {
        const int nbias = qt * 128 + 255;
        for (int i = tid; i < nbias; i += 256)
            bias_full[i] = rel_table[(size_t)(i + (MAXSEQ - 1) - 127) * HEADS + h];
    }

    CP_WAIT0();
    __syncthreads();

    uint32_t qh[4][4], ql[4][4];
    #pragma unroll
    for (int kc = 0; kc < 4; kc++) {
        uint32_t a = sb0 + (uint32_t)((w * 16 + ((l >> 3) & 1) * 8 + (l & 7)) * AP
                                      + kc * 16 + (l >> 4) * 8) * 2;
        LDSM4(qh[kc], a);
        LDSM4(ql[kc], a + 18432);
    }
    __syncthreads();

    float oacc[8][4] = {};
    const int ktmax = 2 * qt + 1;

    const int arr = tid >> 6;
    const int u = tid & 63;
    const size_t krow0 = (size_t)(b * SEQ) * FOURH + 2 * HIDDEN + h * HD;
    const size_t vrow0 = (size_t)((b * HEADS + h) * HD) * SEQ;

    #define ISSUE_STAGE(buf, ktv) do {                                         \
        const uint32_t base_ = sb0 + (uint32_t)(buf) * ST_SZ + arr * 9216;     \
        _Pragma("unroll")                                                      \
        for (int i_ = 0; i_ < 8; i_++) {                                       \
            int r_ = (u >> 3) + 8 * i_;                                        \
            int c_ = u & 7;                                                    \
            const __nv_bfloat16* g_;                                           \
            if (arr == 0)                                                      \
                g_ = g_acthi + krow0 + (size_t)((ktv) * 64 + r_) * FOURH + c_ * 8; \
            else if (arr == 1)                                                 \
                g_ = g_actlo + krow0 + (size_t)((ktv) * 64 + r_) * FOURH + c_ * 8; \
            else if (arr == 2)                                                 \
                g_ = g_vthi + vrow0 + (size_t)r_ * SEQ + (ktv) * 64 + c_ * 8;  \
            else                                                               \
                g_ = g_vtlo + vrow0 + (size_t)r_ * SEQ + (ktv) * 64 + c_ * 8;  \
            CP_ASYNC16(base_ + r_ * 144 + c_ * 16, g_);                        \
        }                                                                      \
    } while (0)

    // prologue: stages 0 and 1 (ktmax >= 1 always)
    ISSUE_STAGE(0, 0);
    CP_COMMIT();
    ISSUE_STAGE(1, 1);
    CP_COMMIT();

    int buf = 0, buf2 = 2;                  // buf = kt%3, buf2 = (kt+2)%3
    for (int kt = 0; kt <= ktmax; kt++) {
        CP_WAIT1();                         // stage kt arrived (kt+1 may fly)
        __syncthreads();                    // all warps done with stage kt-1

        if (kt + 2 <= ktmax)
            ISSUE_STAGE(buf2, kt + 2);      // overwrites buffer read at kt-1: safe
        CP_COMMIT();                        // commit every iter (empty ok)

        const uint32_t stg = sb0 + (uint32_t)buf * ST_SZ;
        const uint32_t offB = (uint32_t)(((l >> 4) * 8 + (l & 7)) * AP
                                         + ((l >> 3) & 1) * 8) * 2;

        // ---- S = Q K^T (3-product) ----
        float sacc[8][4] = {};
        #pragma unroll
        for (int kc = 0; kc < 4; kc++) {
            #pragma unroll
            for (int ntp = 0; ntp < 4; ntp++) {
                uint32_t addr = stg + offB + (uint32_t)(ntp * 16 * AP + kc * 16) * 2;
                uint32_t kh[4], kl[4];
                LDSM4(kh, addr + ST_KH);
                LDSM4(kl, addr + ST_KL);
                #pragma unroll
                for (int t = 0; t < 2; t++) {
                    int nt = ntp * 2 + t;
                    MMA16816(sacc[nt], qh[kc], kh[t * 2], kh[t * 2 + 1]);
                    MMA16816(sacc[nt], qh[kc], kl[t * 2], kl[t * 2 + 1]);
                    MMA16816(sacc[nt], ql[kc], kh[t * 2], kh[t * 2 + 1]);
                }
            }
        }

        // ---- scale + bias + silu + causal mask; split to bf16 hi/lo ----
        const int bbase = qt * 128 - kt * 64 + 127;
        uint32_t shi[8][2], slo[8][2];
        #pragma unroll
        for (int nt = 0; nt < 8; nt++) {
            const int c0 = nt * 8 + (l & 3) * 2;
            const int r0 = w * 16 + (l >> 2);
            float vv[4];
            #pragma unroll
            for (int e = 0; e < 4; e++) {
                int rr = r0 + (e >> 1) * 8;
                int cc = c0 + (e & 1);
                float v = sacc[nt][e] * 0.125f + bias_full[bbase + rr - cc];
                v = silu_f(v);
                vv[e] = ((kt * 64 + cc) <= (qt * 128 + rr)) ? v : 0.0f;
            }
            __nv_bfloat16 h0 = __float2bfloat16(vv[0]);
            __nv_bfloat16 h1 = __float2bfloat16(vv[1]);
            __nv_bfloat16 h2 = __float2bfloat16(vv[2]);
            __nv_bfloat16 h3 = __float2bfloat16(vv[3]);
            shi[nt][0] = pack_bf2(h0, h1);
            shi[nt][1] = pack_bf2(h2, h3);
            slo[nt][0] = pack_bf2(__float2bfloat16(vv[0] - __bfloat162float(h0)),
                                  __float2bfloat16(vv[1] - __bfloat162float(h1)));
            slo[nt][1] = pack_bf2(__float2bfloat16(vv[2] - __bfloat162float(h2)),
                                  __float2bfloat16(vv[3] - __bfloat162float(h3)));
        }

        // ---- out += S @ V (3-product; S accum frags reused as A frags) ----
        #pragma unroll
        for (int kc2 = 0; kc2 < 4; kc2++) {
            uint32_t ah[4] = { shi[2 * kc2][0], shi[2 * kc2][1],
                               shi[2 * kc2 + 1][0], shi[2 * kc2 + 1][1] };
            uint32_t al[4] = { slo[2 * kc2][0], slo[2 * kc2][1],
                               slo[2 * kc2 + 1][0], slo[2 * kc2 + 1][1] };
            #pragma unroll
            for (int ntp = 0; ntp < 4; ntp++) {
                uint32_t addr = stg + offB + (uint32_t)(ntp * 16 * AP + kc2 * 16) * 2;
                uint32_t vh[4], vl[4];
                LDSM4(vh, addr + ST_VH);
                LDSM4(vl, addr + ST_VL);
                #pragma unroll
                for (int t = 0; t < 2; t++) {
                    int nt = ntp * 2 + t;
                    MMA16816(oacc[nt], ah, vh[t * 2], vh[t * 2 + 1]);
                    MMA16816(oacc[nt], ah, vl[t * 2], vl[t * 2 + 1]);
                    MMA16816(oacc[nt], al, vh[t * 2], vh[t * 2 + 1]);
                }
            }
        }

        buf = (buf == 2) ? 0 : buf + 1;
        buf2 = (buf2 == 2) ? 0 : buf2 + 1;
    }
    #undef ISSUE_STAGE

    // ---- epilogue: gated = out * U (U = acthi + actlo), split to bf16 ----
    #pragma unroll
    for (int nt = 0; nt < 8; nt++) {
        const int d0 = nt * 8 + (l & 3) * 2;
        #pragma unroll
        for (int half = 0; half < 2; half++) {
            const int rr = qt * 128 + w * 16 + (l >> 2) + half * 8;
            const size_t grow = (size_t)(b * SEQ + rr);
            const size_t uoff = grow * FOURH + h * HD + d0;
            __nv_bfloat162 uh = *(const __nv_bfloat162*)&g_acthi[uoff];
            __nv_bfloat162 ul = *(const __nv_bfloat162*)&g_actlo[uoff];
            float u0 = __bfloat162float(uh.x) + __bfloat162float(ul.x);
            float u1 = __bfloat162float(uh.y) + __bfloat162float(ul.y);
            float v0 = oacc[nt][half * 2 + 0] * u0;
            float v1 = oacc[nt][half * 2 + 1] * u1;
            __nv_bfloat16 h0 = __float2bfloat16(v0);
            __nv_bfloat16 h1 = __float2bfloat16(v1);
            size_t o = grow * HIDDEN + h * HD + d0;
            *(uint32_t*)&g_ghi[o] = pack_bf2(h0, h1);
            *(uint32_t*)&g_glo[o] =
                pack_bf2(__float2bfloat16(v0 - __bfloat162float(h0)),
                         __float2bfloat16(v1 - __bfloat162float(h1)));
        }
    }
}

// ---------------------------------------------------------------------------
// Launch. Inputs: x, W1, b1, W2, b2, rel_table, attn_mask (ignored: always
// the causal tril by construction; causality applied analytically).
// ---------------------------------------------------------------------------
extern "C" void kernel_launch(void* const* d_in, const int* in_sizes, int n_in,
                              void* d_out, int out_size)
{
    const float* x   = (const float*)d_in[0];
    const float* W1  = (const float*)d_in[1];
    const float* b1  = (const float*)d_in[2];
    const float* W2  = (const float*)d_in[3];
    const float* b2  = (const float*)d_in[4];
    const float* rel = (const float*)d_in[5];
    float* out = (float*)d_out;

    __nv_bfloat16 *acthi, *actlo, *xhi, *xlo, *w1hi, *w1lo, *w2hi, *w2lo, *ghi, *glo;
    cudaGetSymbolAddress((void**)&acthi, g_acthi);
    cudaGetSymbolAddress((void**)&actlo, g_actlo);
    cudaGetSymbolAddress((void**)&xhi, g_xhi);
    cudaGetSymbolAddress((void**)&xlo, g_xlo);
    cudaGetSymbolAddress((void**)&w1hi, g_w1hi);
    cudaGetSymbolAddress((void**)&w1lo, g_w1lo);
    cudaGetSymbolAddress((void**)&w2hi, g_w2hi);
    cudaGetSymbolAddress((void**)&w2lo, g_w2lo);
    cudaGetSymbolAddress((void**)&ghi, g_ghi);
    cudaGetSymbolAddress((void**)&glo, g_glo);

    cudaFuncSetAttribute(mma_gemm, cudaFuncAttributeMaxDynamicSharedMemorySize,
                         GEMM_SMEM);
    cudaFuncSetAttribute(attn_mma, cudaFuncAttributeMaxDynamicSharedMemorySize,
                         ATTN_SMEM);

    // Conversions
    split_kernel<<<(MTOT * HIDDEN) / 256, 256>>>(x, xhi, xlo, MTOT * HIDDEN);
    transpose_split<<<dim3(FOURH / 32, HIDDEN / 32), dim3(32, 8)>>>(W1, w1hi, w1lo,
                                                                    HIDDEN, FOURH);
    transpose_split<<<dim3(HIDDEN / 32, HIDDEN / 32), dim3(32, 8)>>>(W2, w2hi, w2lo,
                                                                     HIDDEN, HIDDEN);
    // GEMM1: activated = silu(x @ W1 + b1) -> bf16 hi/lo only
    mma_gemm<<<dim3(FOURH / 128, MTOT / 128), 128, GEMM_SMEM>>>(
        xhi, xlo, w1hi, w1lo, b1, nullptr, acthi, actlo, FOURH, HIDDEN, 1);
    // V^T (bf16 transpose of act V-region)
    v_transpose_bf16<<<dim3(SEQ / 32, HIDDEN / 32, BATCH), dim3(32, 8)>>>();
    // Tensor-core attention + gating -> g_ghi/g_glo
    attn_mma<<<dim3(SEQ / 128, HEADS, BATCH), 256, ATTN_SMEM>>>(rel);
    // GEMM2: out = gated @ W2 + b2
    mma_gemm<<<dim3(HIDDEN / 128, MTOT / 128), 128, GEMM_SMEM>>>(
        ghi, glo, w2hi, w2lo, b2, out, nullptr, nullptr, HIDDEN, HIDDEN, 0);
}